// round 12
// baseline (speedup 1.0000x reference)
#include <cuda_runtime.h>
#include <cuda_fp16.h>
#include <math.h>
#include <stdint.h>

// Problem constants (fixed shapes)
#define NB   4
#define LQL  2048
#define DM   1024
#define HH   16
#define PP   64
#define MROWS (NB*LQL)        // 8192
#define EPSBN 1e-5f

// ---------------- scratch (device globals: allocation-free) ----------------
__device__ __half gQh [MROWS * DM];   // fp16 Q projection (PRE-SCALED by log2e/32)
__device__ __half gKh [MROWS * DM];
__device__ __half gVh [MROWS * DM];
__device__ __half gAQh[MROWS * DM];
__device__ __half gAKh[MROWS * DM];
__device__ __half gWh [3 * DM * DM];
__device__ float  gRes[MROWS * DM];
__device__ float  gPartS[64 * DM];
__device__ float  gPartQ[64 * DM];
__device__ float  gColA[DM];
__device__ float  gColB[DM];

// ---------------- helpers ----------------
static __device__ __forceinline__ uint32_t smem_u32(const void* p) {
    uint32_t r;
    asm("{ .reg .u64 t; cvta.to.shared.u64 t, %1; cvt.u32.u64 %0, t; }"
        : "=r"(r) : "l"(p));
    return r;
}
static __device__ __forceinline__ void mma_f16(float* d, const uint32_t* a,
                                               uint32_t b0, uint32_t b1)
{
    asm volatile(
        "mma.sync.aligned.m16n8k16.row.col.f32.f16.f16.f32 "
        "{%0,%1,%2,%3}, {%4,%5,%6,%7}, {%8,%9}, {%0,%1,%2,%3};"
        : "+f"(d[0]), "+f"(d[1]), "+f"(d[2]), "+f"(d[3])
        : "r"(a[0]), "r"(a[1]), "r"(a[2]), "r"(a[3]), "r"(b0), "r"(b1));
}
static __device__ __forceinline__ void ldsm_x4(uint32_t* r, uint32_t addr) {
    asm volatile("ldmatrix.sync.aligned.m8n8.x4.shared.b16 {%0,%1,%2,%3}, [%4];"
                 : "=r"(r[0]), "=r"(r[1]), "=r"(r[2]), "=r"(r[3]) : "r"(addr));
}
static __device__ __forceinline__ void ldsm_x2_t(uint32_t& r0, uint32_t& r1,
                                                 uint32_t addr)
{
    asm volatile("ldmatrix.sync.aligned.m8n8.x2.trans.shared.b16 {%0,%1}, [%2];"
                 : "=r"(r0), "=r"(r1) : "r"(addr));
}
static __device__ __forceinline__ float ex2f(float x) {
    float r;
    asm("ex2.approx.f32 %0, %1;" : "=f"(r) : "f"(x));
    return r;
}
static __device__ __forceinline__ uint32_t ex2h2(uint32_t x) {
    uint32_t r;
    asm("ex2.approx.f16x2 %0, %1;" : "=r"(r) : "r"(x));
    return r;
}
#define SWH(r, hc) (((r) << 6) + (((hc) & 7) | ((((hc) >> 3) ^ ((r) & 7)) << 3)))

// ============================================================================
// fused f32 -> f16 conversion pre-pass: 4 float4 per thread for BW
// ============================================================================
__global__ void __launch_bounds__(256) conv_all(const float* __restrict__ q,
                                                const float* __restrict__ k,
                                                const float* __restrict__ wq,
                                                const float* __restrict__ wk,
                                                const float* __restrict__ wv)
{
    const int b = blockIdx.x;
    const float* in;
    __half* out;
    int base;
    if (b < 2048)      { in = q;  out = gAQh;              base = b * 1024; }
    else if (b < 4096) { in = k;  out = gAKh;              base = (b - 2048) * 1024; }
    else if (b < 4352) { in = wq; out = gWh;               base = (b - 4096) * 1024; }
    else if (b < 4608) { in = wk; out = gWh + DM * DM;     base = (b - 4352) * 1024; }
    else               { in = wv; out = gWh + 2 * DM * DM; base = (b - 4608) * 1024; }
    #pragma unroll
    for (int j = 0; j < 4; ++j) {
        int i = base + j * 256 + threadIdx.x;
        float4 v = ((const float4*)in)[i];
        __half2* o = (__half2*)out + 2 * (size_t)i;
        o[0] = __floats2half2_rn(v.x, v.y);
        o[1] = __floats2half2_rn(v.z, v.w);
    }
}

// ============================================================================
// fp16 mma.sync GEMM NT, 3-stage cp.async pipeline.
// z==0 (Q) epilogue pre-scales by (1/32)*log2(e) in fp32 before fp16 store.
// ============================================================================
#define GSTG 8192   // halves per stage per matrix

__global__ void __launch_bounds__(256) gemm_mma()
{
    extern __shared__ __align__(16) __half smh[];
    const int tid  = threadIdx.x;
    const int lane = tid & 31;
    const int wid  = tid >> 5;
    const int g    = lane >> 2;
    const int tg   = lane & 3;
    const int wM   = wid >> 2;
    const int wN   = wid & 3;
    const int n0   = blockIdx.x * 128;
    const int m0   = blockIdx.y * 128;
    const int z    = blockIdx.z;

    const __half* __restrict__ A = (z == 0) ? gAQh : gAKh;
    const __half* __restrict__ W = gWh + (size_t)z * DM * DM;
    __half* __restrict__ C = (z == 0) ? gQh : ((z == 1) ? gKh : gVh);

    uint32_t asA[3], asB[3];
    #pragma unroll
    for (int i = 0; i < 3; ++i) {
        asA[i] = smem_u32(smh + i * GSTG);
        asB[i] = smem_u32(smh + (3 + i) * GSTG);
    }

    float acc[4][4][4] = {};

    const int lr  = tid >> 3;
    const int lc8 = tid & 7;
    const int arow = lane & 15;
    const int asel = lane >> 4;
    const int quad = lane >> 3;
    const int brow = ((quad >> 1) << 3) + (lane & 7);
    const int bsel = quad & 1;

    #pragma unroll
    for (int ps = 0; ps < 2; ++ps) {
        const int k0 = ps * 64;
        #pragma unroll
        for (int it = 0; it < 4; ++it) {
            int r = lr + it * 32;
            uint32_t off = (uint32_t)(r * 128 + ((lc8 ^ (r & 7)) << 4));
            const __half* sa = A + (size_t)(m0 + r) * DM + k0 + lc8 * 8;
            asm volatile("cp.async.cg.shared.global [%0], [%1], 16;"
                         :: "r"(asA[ps] + off), "l"(sa));
            const __half* sb = W + (size_t)(n0 + r) * DM + k0 + lc8 * 8;
            asm volatile("cp.async.cg.shared.global [%0], [%1], 16;"
                         :: "r"(asB[ps] + off), "l"(sb));
        }
        asm volatile("cp.async.commit_group;" ::: "memory");
    }

    const int NSTAGE = DM / 64;   // 16
    int buf = 0, wbuf = 2;
    for (int s = 0; s < NSTAGE; ++s) {
        if (s + 2 < NSTAGE) {
            asm volatile("cp.async.wait_group %0;" :: "n"(1) : "memory");
        } else {
            asm volatile("cp.async.wait_group %0;" :: "n"(0) : "memory");
        }
        __syncthreads();

        if (s + 2 < NSTAGE) {
            const int k0 = (s + 2) * 64;
            #pragma unroll
            for (int it = 0; it < 4; ++it) {
                int r = lr + it * 32;
                uint32_t off = (uint32_t)(r * 128 + ((lc8 ^ (r & 7)) << 4));
                const __half* sa = A + (size_t)(m0 + r) * DM + k0 + lc8 * 8;
                asm volatile("cp.async.cg.shared.global [%0], [%1], 16;"
                             :: "r"(asA[wbuf] + off), "l"(sa));
                const __half* sb = W + (size_t)(n0 + r) * DM + k0 + lc8 * 8;
                asm volatile("cp.async.cg.shared.global [%0], [%1], 16;"
                             :: "r"(asB[wbuf] + off), "l"(sb));
            }
            asm volatile("cp.async.commit_group;" ::: "memory");
        }

        #pragma unroll
        for (int kk = 0; kk < 4; ++kk) {
            uint32_t af[4][4];
            const uint32_t ckA = (uint32_t)(2 * kk + asel);
            #pragma unroll
            for (int mt = 0; mt < 4; ++mt) {
                int row = wM * 64 + mt * 16 + arow;
                uint32_t addr = asA[buf] + (uint32_t)(row * 128)
                              + ((ckA ^ (uint32_t)(row & 7)) << 4);
                ldsm_x4(af[mt], addr);
            }
            uint32_t bf[4][2];
            const uint32_t ckB = (uint32_t)(2 * kk + bsel);
            #pragma unroll
            for (int np = 0; np < 2; ++np) {
                int row = wN * 32 + np * 16 + brow;
                uint32_t addr = asB[buf] + (uint32_t)(row * 128)
                              + ((ckB ^ (uint32_t)(row & 7)) << 4);
                uint32_t t[4];
                ldsm_x4(t, addr);
                bf[2 * np][0] = t[0]; bf[2 * np][1] = t[1];
                bf[2 * np + 1][0] = t[2]; bf[2 * np + 1][1] = t[3];
            }
            #pragma unroll
            for (int mt = 0; mt < 4; ++mt)
                #pragma unroll
                for (int nt = 0; nt < 4; ++nt)
                    mma_f16(acc[mt][nt], af[mt], bf[nt][0], bf[nt][1]);
        }
        buf = (buf + 1) % 3;
        wbuf = (wbuf + 1) % 3;
    }

    // Epilogue: Q gets the softmax pre-scale folded in (fp32, single rounding)
    const float cs = (z == 0) ? 0.045084222f : 1.0f;   // 0.03125*log2(e)
    #pragma unroll
    for (int mt = 0; mt < 4; ++mt) {
        int row = m0 + wM * 64 + mt * 16 + g;
        #pragma unroll
        for (int nt = 0; nt < 4; ++nt) {
            int col = n0 + wN * 32 + nt * 8 + tg * 2;
            *(__half2*)(C + (size_t)row * DM + col) =
                __floats2half2_rn(acc[mt][nt][0] * cs, acc[mt][nt][1] * cs);
            *(__half2*)(C + (size_t)(row + 8) * DM + col) =
                __floats2half2_rn(acc[mt][nt][2] * cs, acc[mt][nt][3] * cs);
        }
    }
}

// ============================================================================
// fp16 mma.sync causal flash attention + fused BN partial stats.
// __launch_bounds__(128, 3): cap regs for 3 CTAs/SM (latency hiding).
// ============================================================================
__global__ void __launch_bounds__(128, 3) attn_mma(const float* __restrict__ query)
{
    extern __shared__ __align__(16) __half ash[];
    __half* Kb[2] = { ash,         ash + 8192 };
    __half* Vb[2] = { ash + 4096,  ash + 12288 };
    __half* Ss    = ash + 16384;
    const uint32_t sK[2] = { smem_u32(Kb[0]), smem_u32(Kb[1]) };
    const uint32_t sV[2] = { smem_u32(Vb[0]), smem_u32(Vb[1]) };
    const uint32_t sS    = smem_u32(Ss);

    const int tid  = threadIdx.x;
    const int lane = tid & 31;
    const int wid  = tid >> 5;
    const int g    = lane >> 2;
    const int tg   = lane & 3;
    const int qt   = (int)(gridDim.x - 1) - (int)blockIdx.x;  // heavy-first
    const int h    = blockIdx.y;
    const int n    = blockIdx.z;

    const size_t nbase = (size_t)n * LQL * DM;
    const int hcol = h * PP;
    const int KT = 2 * qt + 2;

    const int arow = lane & 15;
    const int asel = lane >> 4;
    const int quad = lane >> 3;
    const int brow = ((quad >> 1) << 3) + (lane & 7);
    const int bsel = quad & 1;

    {
        const __half* Kg = gKh + nbase + hcol;
        const __half* Vg = gVh + nbase + hcol;
        #pragma unroll
        for (int i = 0; i < 4; ++i) {
            int idx = tid + i * 128;
            int r = idx >> 3, c8 = idx & 7;
            uint32_t off = (uint32_t)(r * 128 + ((c8 ^ (r & 7)) << 4));
            asm volatile("cp.async.cg.shared.global [%0], [%1], 16;"
                         :: "r"(sK[0] + off), "l"(Kg + (size_t)r * DM + c8 * 8));
            asm volatile("cp.async.cg.shared.global [%0], [%1], 16;"
                         :: "r"(sV[0] + off), "l"(Vg + (size_t)r * DM + c8 * 8));
        }
        asm volatile("cp.async.commit_group;" ::: "memory");
    }

    // Q already pre-scaled in GEMM epilogue: plain staging copy
    {
        const __half* Qg = gQh + nbase + (size_t)qt * 128 * DM + hcol;
        #pragma unroll
        for (int i = 0; i < 8; ++i) {
            int idx = tid + i * 128;
            int r = idx >> 3, c8 = idx & 7;
            uint4 v = *(const uint4*)(Qg + (size_t)r * DM + c8 * 8);
            *(uint4*)(Ss + SWH(r, c8 * 8)) = v;
        }
    }
    __syncthreads();
    uint32_t qf[2][4][4];
    #pragma unroll
    for (int mb = 0; mb < 2; ++mb) {
        int row = wid * 32 + mb * 16 + arow;
        #pragma unroll
        for (int ks = 0; ks < 4; ++ks) {
            uint32_t ck = (uint32_t)(2 * ks + asel);
            uint32_t addr = sS + (uint32_t)(row * 128)
                          + ((ck ^ (uint32_t)(row & 7)) << 4);
            ldsm_x4(qf[mb][ks], addr);
        }
    }
    __syncthreads();

    float o[2][8][4] = {};
    float mrow[2][2], lrow[2][2];
    #pragma unroll
    for (int a = 0; a < 2; ++a)
        #pragma unroll
        for (int b = 0; b < 2; ++b) { mrow[a][b] = -INFINITY; lrow[a][b] = 0.f; }

    for (int kt = 0; kt < KT; ++kt) {
        const int buf = kt & 1;
        if (kt + 1 < KT) {
            const __half* Kg = gKh + nbase + (size_t)(kt + 1) * 64 * DM + hcol;
            const __half* Vg = gVh + nbase + (size_t)(kt + 1) * 64 * DM + hcol;
            #pragma unroll
            for (int i = 0; i < 4; ++i) {
                int idx = tid + i * 128;
                int r = idx >> 3, c8 = idx & 7;
                uint32_t off = (uint32_t)(r * 128 + ((c8 ^ (r & 7)) << 4));
                asm volatile("cp.async.cg.shared.global [%0], [%1], 16;"
                             :: "r"(sK[buf ^ 1] + off), "l"(Kg + (size_t)r * DM + c8 * 8));
                asm volatile("cp.async.cg.shared.global [%0], [%1], 16;"
                             :: "r"(sV[buf ^ 1] + off), "l"(Vg + (size_t)r * DM + c8 * 8));
            }
            asm volatile("cp.async.commit_group;" ::: "memory");
            asm volatile("cp.async.wait_group %0;" :: "n"(1) : "memory");
        } else {
            asm volatile("cp.async.wait_group %0;" :: "n"(0) : "memory");
        }
        __syncthreads();

        float s[2][8][4] = {};
        #pragma unroll
        for (int ks = 0; ks < 4; ++ks) {
            const uint32_t ck = (uint32_t)(2 * ks + bsel);
            #pragma unroll
            for (int nbp = 0; nbp < 4; ++nbp) {
                int row = nbp * 16 + brow;
                uint32_t addr = sK[buf] + (uint32_t)(row * 128)
                              + ((ck ^ (uint32_t)(row & 7)) << 4);
                uint32_t t[4];
                ldsm_x4(t, addr);
                mma_f16(s[0][2 * nbp],     qf[0][ks], t[0], t[1]);
                mma_f16(s[1][2 * nbp],     qf[1][ks], t[0], t[1]);
                mma_f16(s[0][2 * nbp + 1], qf[0][ks], t[2], t[3]);
                mma_f16(s[1][2 * nbp + 1], qf[1][ks], t[2], t[3]);
            }
        }

        const bool tail = (kt >= 2 * qt);
        #pragma unroll
        for (int mb = 0; mb < 2; ++mb) {
            #pragma unroll
            for (int rr = 0; rr < 2; ++rr) {
                const int rloc = wid * 32 + mb * 16 + rr * 8 + g;
                const int grow = qt * 128 + rloc;
                float tm = -INFINITY;
                #pragma unroll
                for (int nb = 0; nb < 8; ++nb) {
                    float v0 = s[mb][nb][rr * 2 + 0];
                    float v1 = s[mb][nb][rr * 2 + 1];
                    if (tail) {
                        int c0 = kt * 64 + nb * 8 + tg * 2;
                        if (c0     > grow) v0 = -1e30f;
                        if (c0 + 1 > grow) v1 = -1e30f;
                    }
                    s[mb][nb][rr * 2 + 0] = v0;
                    s[mb][nb][rr * 2 + 1] = v1;
                    tm = fmaxf(tm, fmaxf(v0, v1));
                }
                tm = fmaxf(tm, __shfl_xor_sync(0xffffffffu, tm, 1));
                tm = fmaxf(tm, __shfl_xor_sync(0xffffffffu, tm, 2));
                float nm   = fmaxf(mrow[mb][rr], tm);
                float corr = ex2f(mrow[mb][rr] - nm);
                mrow[mb][rr] = nm;
                float rs = 0.f;
                #pragma unroll
                for (int nb = 0; nb < 8; ++nb) {
                    __half2 a2 = __floats2half2_rn(s[mb][nb][rr * 2 + 0] - nm,
                                                   s[mb][nb][rr * 2 + 1] - nm);
                    uint32_t p2 = ex2h2(*(uint32_t*)&a2);
                    *(uint32_t*)(Ss + SWH(rloc, nb * 8 + 2 * tg)) = p2;
                    float2 pf = __half22float2(*(__half2*)&p2);
                    rs += pf.x + pf.y;
                }
                rs += __shfl_xor_sync(0xffffffffu, rs, 1);
                rs += __shfl_xor_sync(0xffffffffu, rs, 2);
                lrow[mb][rr] = lrow[mb][rr] * corr + rs;
                #pragma unroll
                for (int nb = 0; nb < 8; ++nb) {
                    o[mb][nb][rr * 2 + 0] *= corr;
                    o[mb][nb][rr * 2 + 1] *= corr;
                }
            }
        }

        #pragma unroll
        for (int ks = 0; ks < 4; ++ks) {
            uint32_t af[2][4];
            const uint32_t ckP = (uint32_t)(2 * ks + asel);
            #pragma unroll
            for (int mb = 0; mb < 2; ++mb) {
                int row = wid * 32 + mb * 16 + arow;
                uint32_t addr = sS + (uint32_t)(row * 128)
                              + ((ckP ^ (uint32_t)(row & 7)) << 4);
                ldsm_x4(af[mb], addr);
            }
            const int vrow = ks * 16 + (lane & 15);
            const uint32_t rowbase = sV[buf] + (uint32_t)vrow * 128u;
            const uint32_t rx = (uint32_t)(vrow & 7) << 4;
            #pragma unroll
            for (int nb = 0; nb < 8; ++nb) {
                uint32_t addr = rowbase + (((uint32_t)nb << 4) ^ rx);
                uint32_t b0, b1;
                ldsm_x2_t(b0, b1, addr);
                mma_f16(o[0][nb], af[0], b0, b1);
                mma_f16(o[1][nb], af[1], b0, b1);
            }
        }
        __syncthreads();
    }

    // ---- epilogue: normalize, residual add, write gRes, fused col stats ----
    float colS[16], colQ[16];
    #pragma unroll
    for (int i = 0; i < 16; ++i) { colS[i] = 0.f; colQ[i] = 0.f; }

    #pragma unroll
    for (int mb = 0; mb < 2; ++mb) {
        #pragma unroll
        for (int rr = 0; rr < 2; ++rr) {
            float inv = 1.0f / lrow[mb][rr];
            int grow = qt * 128 + wid * 32 + mb * 16 + rr * 8 + g;
            size_t rowoff = nbase + (size_t)grow * DM + hcol;
            #pragma unroll
            for (int nb = 0; nb < 8; ++nb) {
                int c = nb * 8 + tg * 2;
                float2 qv = *(const float2*)(query + rowoff + c);
                float2 w;
                w.x = o[mb][nb][rr * 2 + 0] * inv + qv.x;
                w.y = o[mb][nb][rr * 2 + 1] * inv + qv.y;
                *(float2*)(gRes + rowoff + c) = w;
                colS[2 * nb]     += w.x;
                colQ[2 * nb]     += w.x * w.x;
                colS[2 * nb + 1] += w.y;
                colQ[2 * nb + 1] += w.y * w.y;
            }
        }
    }
    #pragma unroll
    for (int i = 0; i < 16; ++i) {
        #pragma unroll
        for (int off = 4; off < 32; off <<= 1) {
            colS[i] += __shfl_xor_sync(0xffffffffu, colS[i], off);
            colQ[i] += __shfl_xor_sync(0xffffffffu, colQ[i], off);
        }
    }
    float* redS = (float*)ash;          // [4][64]
    float* redQ = redS + 256;           // [4][64]
    if (g == 0) {
        #pragma unroll
        for (int i = 0; i < 16; ++i) {
            int c = (i >> 1) * 8 + tg * 2 + (i & 1);
            redS[wid * 64 + c] = colS[i];
            redQ[wid * 64 + c] = colQ[i];
        }
    }
    __syncthreads();
    if (tid < 64) {
        float s = redS[tid] + redS[64 + tid] + redS[128 + tid] + redS[192 + tid];
        float q = redQ[tid] + redQ[64 + tid] + redQ[128 + tid] + redQ[192 + tid];
        int chunk = n * 16 + qt;
        gPartS[chunk * DM + hcol + tid] = s;
        gPartQ[chunk * DM + hcol + tid] = q;
    }
}

// ---------------------------------------------------------------------------
// BatchNorm: final stats + fused normalize
// ---------------------------------------------------------------------------
__global__ void __launch_bounds__(256) colstats_final(const float* __restrict__ gamma,
                                                      const float* __restrict__ beta)
{
    const int cidx = threadIdx.x & 31;
    const int seg  = threadIdx.x >> 5;
    const int col  = blockIdx.x * 32 + cidx;
    float s = 0.f, q = 0.f;
    #pragma unroll
    for (int c = 0; c < 8; ++c) {
        int chunk = seg * 8 + c;
        s += gPartS[chunk * DM + col];
        q += gPartQ[chunk * DM + col];
    }
    __shared__ float shS[8][33], shQ[8][33];
    shS[seg][cidx] = s;
    shQ[seg][cidx] = q;
    __syncthreads();
    if (seg == 0) {
        float ts = 0.f, tq = 0.f;
        #pragma unroll
        for (int i = 0; i < 8; ++i) { ts += shS[i][cidx]; tq += shQ[i][cidx]; }
        const float invn = 1.0f / (float)MROWS;
        float mean = ts * invn;
        float var  = tq * invn - mean * mean;
        float inv  = rsqrtf(var + EPSBN);
        float a    = gamma[col] * inv;
        gColA[col] = a;
        gColB[col] = beta[col] - mean * a;
    }
}

__global__ void __launch_bounds__(256) normalize_kernel(float* __restrict__ out)
{
    const size_t idx = (size_t)blockIdx.x * 256 + threadIdx.x;
    float4 v = ((const float4*)gRes)[idx];
    int col = (int)((idx * 4) & (DM - 1));
    float4 r;
    r.x = v.x * gColA[col + 0] + gColB[col + 0];
    r.y = v.y * gColA[col + 1] + gColB[col + 1];
    r.z = v.z * gColA[col + 2] + gColB[col + 2];
    r.w = v.w * gColA[col + 3] + gColB[col + 3];
    ((float4*)out)[idx] = r;
}

// ---------------------------------------------------------------------------
extern "C" void kernel_launch(void* const* d_in, const int* in_sizes, int n_in,
                              void* d_out, int out_size)
{
    const float* query = (const float*)d_in[0];
    const float* key   = (const float*)d_in[1];
    const float* Wq    = (const float*)d_in[2];
    const float* Wk    = (const float*)d_in[3];
    const float* Wv    = (const float*)d_in[4];
    const float* gamma = (const float*)d_in[5];
    const float* beta  = (const float*)d_in[6];
    float* out = (float*)d_out;

    conv_all<<<4864, 256>>>(query, key, Wq, Wk, Wv);

    const int gemm_smem = 6 * GSTG * 2;      // 98304 B
    cudaFuncSetAttribute(gemm_mma, cudaFuncAttributeMaxDynamicSharedMemorySize,
                         gemm_smem);
    dim3 gg(DM / 128, MROWS / 128, 3);
    gemm_mma<<<gg, 256, gemm_smem>>>();

    const int attn_smem = 24576 * 2;         // 49152 B
    cudaFuncSetAttribute(attn_mma, cudaFuncAttributeMaxDynamicSharedMemorySize,
                         attn_smem);
    dim3 ga(LQL / 128, HH, NB);
    attn_mma<<<ga, 128, attn_smem>>>(query);

    colstats_final<<<DM / 32, 256>>>(gamma, beta);

    const int total_f4 = MROWS * DM / 4;
    normalize_kernel<<<total_f4 / 256, 256>>>(out);
}

// round 13
// speedup vs baseline: 1.0305x; 1.0305x over previous
#include <cuda_runtime.h>
#include <cuda_fp16.h>
#include <math.h>
#include <stdint.h>

// Problem constants (fixed shapes)
#define NB   4
#define LQL  2048
#define DM   1024
#define HH   16
#define PP   64
#define MROWS (NB*LQL)        // 8192
#define EPSBN 1e-5f

// ---------------- scratch (device globals: allocation-free) ----------------
__device__ __half gQh [MROWS * DM];   // fp16 Q projection (PRE-SCALED by log2e/32)
__device__ __half gKh [MROWS * DM];
__device__ __half gVh [MROWS * DM];
__device__ __half gAQh[MROWS * DM];
__device__ __half gAKh[MROWS * DM];
__device__ __half gWh [3 * DM * DM];
__device__ float  gRes[MROWS * DM];
__device__ float  gPartS[64 * DM];
__device__ float  gPartQ[64 * DM];
__device__ float  gColA[DM];
__device__ float  gColB[DM];

// ---------------- helpers ----------------
static __device__ __forceinline__ uint32_t smem_u32(const void* p) {
    uint32_t r;
    asm("{ .reg .u64 t; cvta.to.shared.u64 t, %1; cvt.u32.u64 %0, t; }"
        : "=r"(r) : "l"(p));
    return r;
}
static __device__ __forceinline__ void mma_f16(float* d, const uint32_t* a,
                                               uint32_t b0, uint32_t b1)
{
    asm volatile(
        "mma.sync.aligned.m16n8k16.row.col.f32.f16.f16.f32 "
        "{%0,%1,%2,%3}, {%4,%5,%6,%7}, {%8,%9}, {%0,%1,%2,%3};"
        : "+f"(d[0]), "+f"(d[1]), "+f"(d[2]), "+f"(d[3])
        : "r"(a[0]), "r"(a[1]), "r"(a[2]), "r"(a[3]), "r"(b0), "r"(b1));
}
static __device__ __forceinline__ void ldsm_x4(uint32_t* r, uint32_t addr) {
    asm volatile("ldmatrix.sync.aligned.m8n8.x4.shared.b16 {%0,%1,%2,%3}, [%4];"
                 : "=r"(r[0]), "=r"(r[1]), "=r"(r[2]), "=r"(r[3]) : "r"(addr));
}
static __device__ __forceinline__ void ldsm_x2_t(uint32_t& r0, uint32_t& r1,
                                                 uint32_t addr)
{
    asm volatile("ldmatrix.sync.aligned.m8n8.x2.trans.shared.b16 {%0,%1}, [%2];"
                 : "=r"(r0), "=r"(r1) : "r"(addr));
}
static __device__ __forceinline__ float ex2f(float x) {
    float r;
    asm("ex2.approx.f32 %0, %1;" : "=f"(r) : "f"(x));
    return r;
}
static __device__ __forceinline__ uint32_t ex2h2(uint32_t x) {
    uint32_t r;
    asm("ex2.approx.f16x2 %0, %1;" : "=r"(r) : "r"(x));
    return r;
}
#define SWH(r, hc) (((r) << 6) + (((hc) & 7) | ((((hc) >> 3) ^ ((r) & 7)) << 3)))

// ============================================================================
// fused f32 -> f16 conversion pre-pass: 4 float4 per thread for BW
// ============================================================================
__global__ void __launch_bounds__(256) conv_all(const float* __restrict__ q,
                                                const float* __restrict__ k,
                                                const float* __restrict__ wq,
                                                const float* __restrict__ wk,
                                                const float* __restrict__ wv)
{
    const int b = blockIdx.x;
    const float* in;
    __half* out;
    int base;
    if (b < 2048)      { in = q;  out = gAQh;              base = b * 1024; }
    else if (b < 4096) { in = k;  out = gAKh;              base = (b - 2048) * 1024; }
    else if (b < 4352) { in = wq; out = gWh;               base = (b - 4096) * 1024; }
    else if (b < 4608) { in = wk; out = gWh + DM * DM;     base = (b - 4352) * 1024; }
    else               { in = wv; out = gWh + 2 * DM * DM; base = (b - 4608) * 1024; }
    #pragma unroll
    for (int j = 0; j < 4; ++j) {
        int i = base + j * 256 + threadIdx.x;
        float4 v = ((const float4*)in)[i];
        __half2* o = (__half2*)out + 2 * (size_t)i;
        o[0] = __floats2half2_rn(v.x, v.y);
        o[1] = __floats2half2_rn(v.z, v.w);
    }
}

// ============================================================================
// fp16 mma.sync GEMM NT, 3-stage cp.async pipeline.
// z==0 (Q) epilogue pre-scales by (1/32)*log2(e) in fp32 before fp16 store.
// ============================================================================
#define GSTG 8192   // halves per stage per matrix

__global__ void __launch_bounds__(256) gemm_mma()
{
    extern __shared__ __align__(16) __half smh[];
    const int tid  = threadIdx.x;
    const int lane = tid & 31;
    const int wid  = tid >> 5;
    const int g    = lane >> 2;
    const int tg   = lane & 3;
    const int wM   = wid >> 2;
    const int wN   = wid & 3;
    const int n0   = blockIdx.x * 128;
    const int m0   = blockIdx.y * 128;
    const int z    = blockIdx.z;

    const __half* __restrict__ A = (z == 0) ? gAQh : gAKh;
    const __half* __restrict__ W = gWh + (size_t)z * DM * DM;
    __half* __restrict__ C = (z == 0) ? gQh : ((z == 1) ? gKh : gVh);

    uint32_t asA[3], asB[3];
    #pragma unroll
    for (int i = 0; i < 3; ++i) {
        asA[i] = smem_u32(smh + i * GSTG);
        asB[i] = smem_u32(smh + (3 + i) * GSTG);
    }

    float acc[4][4][4] = {};

    const int lr  = tid >> 3;
    const int lc8 = tid & 7;
    const int arow = lane & 15;
    const int asel = lane >> 4;
    const int quad = lane >> 3;
    const int brow = ((quad >> 1) << 3) + (lane & 7);
    const int bsel = quad & 1;

    #pragma unroll
    for (int ps = 0; ps < 2; ++ps) {
        const int k0 = ps * 64;
        #pragma unroll
        for (int it = 0; it < 4; ++it) {
            int r = lr + it * 32;
            uint32_t off = (uint32_t)(r * 128 + ((lc8 ^ (r & 7)) << 4));
            const __half* sa = A + (size_t)(m0 + r) * DM + k0 + lc8 * 8;
            asm volatile("cp.async.cg.shared.global [%0], [%1], 16;"
                         :: "r"(asA[ps] + off), "l"(sa));
            const __half* sb = W + (size_t)(n0 + r) * DM + k0 + lc8 * 8;
            asm volatile("cp.async.cg.shared.global [%0], [%1], 16;"
                         :: "r"(asB[ps] + off), "l"(sb));
        }
        asm volatile("cp.async.commit_group;" ::: "memory");
    }

    const int NSTAGE = DM / 64;   // 16
    int buf = 0, wbuf = 2;
    for (int s = 0; s < NSTAGE; ++s) {
        if (s + 2 < NSTAGE) {
            asm volatile("cp.async.wait_group %0;" :: "n"(1) : "memory");
        } else {
            asm volatile("cp.async.wait_group %0;" :: "n"(0) : "memory");
        }
        __syncthreads();

        if (s + 2 < NSTAGE) {
            const int k0 = (s + 2) * 64;
            #pragma unroll
            for (int it = 0; it < 4; ++it) {
                int r = lr + it * 32;
                uint32_t off = (uint32_t)(r * 128 + ((lc8 ^ (r & 7)) << 4));
                const __half* sa = A + (size_t)(m0 + r) * DM + k0 + lc8 * 8;
                asm volatile("cp.async.cg.shared.global [%0], [%1], 16;"
                             :: "r"(asA[wbuf] + off), "l"(sa));
                const __half* sb = W + (size_t)(n0 + r) * DM + k0 + lc8 * 8;
                asm volatile("cp.async.cg.shared.global [%0], [%1], 16;"
                             :: "r"(asB[wbuf] + off), "l"(sb));
            }
            asm volatile("cp.async.commit_group;" ::: "memory");
        }

        #pragma unroll
        for (int kk = 0; kk < 4; ++kk) {
            uint32_t af[4][4];
            const uint32_t ckA = (uint32_t)(2 * kk + asel);
            #pragma unroll
            for (int mt = 0; mt < 4; ++mt) {
                int row = wM * 64 + mt * 16 + arow;
                uint32_t addr = asA[buf] + (uint32_t)(row * 128)
                              + ((ckA ^ (uint32_t)(row & 7)) << 4);
                ldsm_x4(af[mt], addr);
            }
            uint32_t bf[4][2];
            const uint32_t ckB = (uint32_t)(2 * kk + bsel);
            #pragma unroll
            for (int np = 0; np < 2; ++np) {
                int row = wN * 32 + np * 16 + brow;
                uint32_t addr = asB[buf] + (uint32_t)(row * 128)
                              + ((ckB ^ (uint32_t)(row & 7)) << 4);
                uint32_t t[4];
                ldsm_x4(t, addr);
                bf[2 * np][0] = t[0]; bf[2 * np][1] = t[1];
                bf[2 * np + 1][0] = t[2]; bf[2 * np + 1][1] = t[3];
            }
            #pragma unroll
            for (int mt = 0; mt < 4; ++mt)
                #pragma unroll
                for (int nt = 0; nt < 4; ++nt)
                    mma_f16(acc[mt][nt], af[mt], bf[nt][0], bf[nt][1]);
        }
        buf = (buf + 1) % 3;
        wbuf = (wbuf + 1) % 3;
    }

    // Epilogue: Q gets the softmax pre-scale folded in (fp32, single rounding)
    const float cs = (z == 0) ? 0.045084222f : 1.0f;   // 0.03125*log2(e)
    #pragma unroll
    for (int mt = 0; mt < 4; ++mt) {
        int row = m0 + wM * 64 + mt * 16 + g;
        #pragma unroll
        for (int nt = 0; nt < 4; ++nt) {
            int col = n0 + wN * 32 + nt * 8 + tg * 2;
            *(__half2*)(C + (size_t)row * DM + col) =
                __floats2half2_rn(acc[mt][nt][0] * cs, acc[mt][nt][1] * cs);
            *(__half2*)(C + (size_t)(row + 8) * DM + col) =
                __floats2half2_rn(acc[mt][nt][2] * cs, acc[mt][nt][3] * cs);
        }
    }
}

// ============================================================================
// fp16 mma.sync causal flash attention + fused BN partial stats.
// Natural occupancy (2 CTAs/SM, no register cap — R12 showed spills cost more).
// ============================================================================
__global__ void __launch_bounds__(128) attn_mma(const float* __restrict__ query)
{
    extern __shared__ __align__(16) __half ash[];
    __half* Kb[2] = { ash,         ash + 8192 };
    __half* Vb[2] = { ash + 4096,  ash + 12288 };
    __half* Ss    = ash + 16384;
    const uint32_t sK[2] = { smem_u32(Kb[0]), smem_u32(Kb[1]) };
    const uint32_t sV[2] = { smem_u32(Vb[0]), smem_u32(Vb[1]) };
    const uint32_t sS    = smem_u32(Ss);

    const int tid  = threadIdx.x;
    const int lane = tid & 31;
    const int wid  = tid >> 5;
    const int g    = lane >> 2;
    const int tg   = lane & 3;
    const int qt   = (int)(gridDim.x - 1) - (int)blockIdx.x;  // heavy-first
    const int h    = blockIdx.y;
    const int n    = blockIdx.z;

    const size_t nbase = (size_t)n * LQL * DM;
    const int hcol = h * PP;
    const int KT = 2 * qt + 2;

    const int arow = lane & 15;
    const int asel = lane >> 4;
    const int quad = lane >> 3;
    const int brow = ((quad >> 1) << 3) + (lane & 7);
    const int bsel = quad & 1;

    // ---- prefetch K/V tile 0 + stage Q via cp.async (overlapped) ----
    {
        const __half* Kg = gKh + nbase + hcol;
        const __half* Vg = gVh + nbase + hcol;
        #pragma unroll
        for (int i = 0; i < 4; ++i) {
            int idx = tid + i * 128;
            int r = idx >> 3, c8 = idx & 7;
            uint32_t off = (uint32_t)(r * 128 + ((c8 ^ (r & 7)) << 4));
            asm volatile("cp.async.cg.shared.global [%0], [%1], 16;"
                         :: "r"(sK[0] + off), "l"(Kg + (size_t)r * DM + c8 * 8));
            asm volatile("cp.async.cg.shared.global [%0], [%1], 16;"
                         :: "r"(sV[0] + off), "l"(Vg + (size_t)r * DM + c8 * 8));
        }
        // Q staging (pre-scaled in GEMM): cp.async into Ss
        const __half* Qg = gQh + nbase + (size_t)qt * 128 * DM + hcol;
        #pragma unroll
        for (int i = 0; i < 8; ++i) {
            int idx = tid + i * 128;
            int r = idx >> 3, c8 = idx & 7;
            uint32_t off = (uint32_t)(r * 128 + ((c8 ^ (r & 7)) << 4));
            asm volatile("cp.async.cg.shared.global [%0], [%1], 16;"
                         :: "r"(sS + off), "l"(Qg + (size_t)r * DM + c8 * 8));
        }
        asm volatile("cp.async.commit_group;" ::: "memory");
    }

    asm volatile("cp.async.wait_group %0;" :: "n"(0) : "memory");
    __syncthreads();
    uint32_t qf[2][4][4];
    #pragma unroll
    for (int mb = 0; mb < 2; ++mb) {
        int row = wid * 32 + mb * 16 + arow;
        #pragma unroll
        for (int ks = 0; ks < 4; ++ks) {
            uint32_t ck = (uint32_t)(2 * ks + asel);
            uint32_t addr = sS + (uint32_t)(row * 128)
                          + ((ck ^ (uint32_t)(row & 7)) << 4);
            ldsm_x4(qf[mb][ks], addr);
        }
    }
    __syncthreads();

    float o[2][8][4] = {};
    float mrow[2][2], lrow[2][2];
    #pragma unroll
    for (int a = 0; a < 2; ++a)
        #pragma unroll
        for (int b = 0; b < 2; ++b) { mrow[a][b] = -INFINITY; lrow[a][b] = 0.f; }

    for (int kt = 0; kt < KT; ++kt) {
        const int buf = kt & 1;
        if (kt + 1 < KT) {
            const __half* Kg = gKh + nbase + (size_t)(kt + 1) * 64 * DM + hcol;
            const __half* Vg = gVh + nbase + (size_t)(kt + 1) * 64 * DM + hcol;
            #pragma unroll
            for (int i = 0; i < 4; ++i) {
                int idx = tid + i * 128;
                int r = idx >> 3, c8 = idx & 7;
                uint32_t off = (uint32_t)(r * 128 + ((c8 ^ (r & 7)) << 4));
                asm volatile("cp.async.cg.shared.global [%0], [%1], 16;"
                             :: "r"(sK[buf ^ 1] + off), "l"(Kg + (size_t)r * DM + c8 * 8));
                asm volatile("cp.async.cg.shared.global [%0], [%1], 16;"
                             :: "r"(sV[buf ^ 1] + off), "l"(Vg + (size_t)r * DM + c8 * 8));
            }
            asm volatile("cp.async.commit_group;" ::: "memory");
            asm volatile("cp.async.wait_group %0;" :: "n"(1) : "memory");
        } else {
            asm volatile("cp.async.wait_group %0;" :: "n"(0) : "memory");
        }
        __syncthreads();

        float s[2][8][4] = {};
        #pragma unroll
        for (int ks = 0; ks < 4; ++ks) {
            const uint32_t ck = (uint32_t)(2 * ks + bsel);
            #pragma unroll
            for (int nbp = 0; nbp < 4; ++nbp) {
                int row = nbp * 16 + brow;
                uint32_t addr = sK[buf] + (uint32_t)(row * 128)
                              + ((ck ^ (uint32_t)(row & 7)) << 4);
                uint32_t t[4];
                ldsm_x4(t, addr);
                mma_f16(s[0][2 * nbp],     qf[0][ks], t[0], t[1]);
                mma_f16(s[1][2 * nbp],     qf[1][ks], t[0], t[1]);
                mma_f16(s[0][2 * nbp + 1], qf[0][ks], t[2], t[3]);
                mma_f16(s[1][2 * nbp + 1], qf[1][ks], t[2], t[3]);
            }
        }

        const bool tail = (kt >= 2 * qt);
        #pragma unroll
        for (int mb = 0; mb < 2; ++mb) {
            #pragma unroll
            for (int rr = 0; rr < 2; ++rr) {
                const int rloc = wid * 32 + mb * 16 + rr * 8 + g;
                const int grow = qt * 128 + rloc;
                float tm = -INFINITY;
                #pragma unroll
                for (int nb = 0; nb < 8; ++nb) {
                    float v0 = s[mb][nb][rr * 2 + 0];
                    float v1 = s[mb][nb][rr * 2 + 1];
                    if (tail) {
                        int c0 = kt * 64 + nb * 8 + tg * 2;
                        if (c0     > grow) v0 = -1e30f;
                        if (c0 + 1 > grow) v1 = -1e30f;
                    }
                    s[mb][nb][rr * 2 + 0] = v0;
                    s[mb][nb][rr * 2 + 1] = v1;
                    tm = fmaxf(tm, fmaxf(v0, v1));
                }
                tm = fmaxf(tm, __shfl_xor_sync(0xffffffffu, tm, 1));
                tm = fmaxf(tm, __shfl_xor_sync(0xffffffffu, tm, 2));
                float nm   = fmaxf(mrow[mb][rr], tm);
                float corr = ex2f(mrow[mb][rr] - nm);
                mrow[mb][rr] = nm;
                float rs = 0.f;
                #pragma unroll
                for (int nb = 0; nb < 8; ++nb) {
                    __half2 a2 = __floats2half2_rn(s[mb][nb][rr * 2 + 0] - nm,
                                                   s[mb][nb][rr * 2 + 1] - nm);
                    uint32_t p2 = ex2h2(*(uint32_t*)&a2);
                    *(uint32_t*)(Ss + SWH(rloc, nb * 8 + 2 * tg)) = p2;
                    float2 pf = __half22float2(*(__half2*)&p2);
                    rs += pf.x + pf.y;
                }
                rs += __shfl_xor_sync(0xffffffffu, rs, 1);
                rs += __shfl_xor_sync(0xffffffffu, rs, 2);
                lrow[mb][rr] = lrow[mb][rr] * corr + rs;
                #pragma unroll
                for (int nb = 0; nb < 8; ++nb) {
                    o[mb][nb][rr * 2 + 0] *= corr;
                    o[mb][nb][rr * 2 + 1] *= corr;
                }
            }
        }

        #pragma unroll
        for (int ks = 0; ks < 4; ++ks) {
            uint32_t af[2][4];
            const uint32_t ckP = (uint32_t)(2 * ks + asel);
            #pragma unroll
            for (int mb = 0; mb < 2; ++mb) {
                int row = wid * 32 + mb * 16 + arow;
                uint32_t addr = sS + (uint32_t)(row * 128)
                              + ((ckP ^ (uint32_t)(row & 7)) << 4);
                ldsm_x4(af[mb], addr);
            }
            const int vrow = ks * 16 + (lane & 15);
            const uint32_t rowbase = sV[buf] + (uint32_t)vrow * 128u;
            const uint32_t rx = (uint32_t)(vrow & 7) << 4;
            #pragma unroll
            for (int nb = 0; nb < 8; ++nb) {
                uint32_t addr = rowbase + (((uint32_t)nb << 4) ^ rx);
                uint32_t b0, b1;
                ldsm_x2_t(b0, b1, addr);
                mma_f16(o[0][nb], af[0], b0, b1);
                mma_f16(o[1][nb], af[1], b0, b1);
            }
        }
        __syncthreads();
    }

    // ---- epilogue: normalize, residual add, write gRes, fused col stats ----
    float colS[16], colQ[16];
    #pragma unroll
    for (int i = 0; i < 16; ++i) { colS[i] = 0.f; colQ[i] = 0.f; }

    #pragma unroll
    for (int mb = 0; mb < 2; ++mb) {
        #pragma unroll
        for (int rr = 0; rr < 2; ++rr) {
            float inv = 1.0f / lrow[mb][rr];
            int grow = qt * 128 + wid * 32 + mb * 16 + rr * 8 + g;
            size_t rowoff = nbase + (size_t)grow * DM + hcol;
            #pragma unroll
            for (int nb = 0; nb < 8; ++nb) {
                int c = nb * 8 + tg * 2;
                float2 qv = *(const float2*)(query + rowoff + c);
                float2 w;
                w.x = o[mb][nb][rr * 2 + 0] * inv + qv.x;
                w.y = o[mb][nb][rr * 2 + 1] * inv + qv.y;
                *(float2*)(gRes + rowoff + c) = w;
                colS[2 * nb]     += w.x;
                colQ[2 * nb]     += w.x * w.x;
                colS[2 * nb + 1] += w.y;
                colQ[2 * nb + 1] += w.y * w.y;
            }
        }
    }
    #pragma unroll
    for (int i = 0; i < 16; ++i) {
        #pragma unroll
        for (int off = 4; off < 32; off <<= 1) {
            colS[i] += __shfl_xor_sync(0xffffffffu, colS[i], off);
            colQ[i] += __shfl_xor_sync(0xffffffffu, colQ[i], off);
        }
    }
    float* redS = (float*)ash;          // [4][64]
    float* redQ = redS + 256;           // [4][64]
    if (g == 0) {
        #pragma unroll
        for (int i = 0; i < 16; ++i) {
            int c = (i >> 1) * 8 + tg * 2 + (i & 1);
            redS[wid * 64 + c] = colS[i];
            redQ[wid * 64 + c] = colQ[i];
        }
    }
    __syncthreads();
    if (tid < 64) {
        float s = redS[tid] + redS[64 + tid] + redS[128 + tid] + redS[192 + tid];
        float q = redQ[tid] + redQ[64 + tid] + redQ[128 + tid] + redQ[192 + tid];
        int chunk = n * 16 + qt;
        gPartS[chunk * DM + hcol + tid] = s;
        gPartQ[chunk * DM + hcol + tid] = q;
    }
}

// ---------------------------------------------------------------------------
// BatchNorm: final stats + fused normalize
// ---------------------------------------------------------------------------
__global__ void __launch_bounds__(256) colstats_final(const float* __restrict__ gamma,
                                                      const float* __restrict__ beta)
{
    const int cidx = threadIdx.x & 31;
    const int seg  = threadIdx.x >> 5;
    const int col  = blockIdx.x * 32 + cidx;
    float s = 0.f, q = 0.f;
    #pragma unroll
    for (int c = 0; c < 8; ++c) {
        int chunk = seg * 8 + c;
        s += gPartS[chunk * DM + col];
        q += gPartQ[chunk * DM + col];
    }
    __shared__ float shS[8][33], shQ[8][33];
    shS[seg][cidx] = s;
    shQ[seg][cidx] = q;
    __syncthreads();
    if (seg == 0) {
        float ts = 0.f, tq = 0.f;
        #pragma unroll
        for (int i = 0; i < 8; ++i) { ts += shS[i][cidx]; tq += shQ[i][cidx]; }
        const float invn = 1.0f / (float)MROWS;
        float mean = ts * invn;
        float var  = tq * invn - mean * mean;
        float inv  = rsqrtf(var + EPSBN);
        float a    = gamma[col] * inv;
        gColA[col] = a;
        gColB[col] = beta[col] - mean * a;
    }
}

// 4 float4 per thread: fewer blocks, more ILP on a pure-BW kernel
__global__ void __launch_bounds__(256) normalize_kernel(float* __restrict__ out)
{
    const size_t base = (size_t)blockIdx.x * 1024 + threadIdx.x;
    #pragma unroll
    for (int j = 0; j < 4; ++j) {
        const size_t idx = base + j * 256;
        float4 v = ((const float4*)gRes)[idx];
        int col = (int)((idx * 4) & (DM - 1));
        float4 r;
        r.x = v.x * gColA[col + 0] + gColB[col + 0];
        r.y = v.y * gColA[col + 1] + gColB[col + 1];
        r.z = v.z * gColA[col + 2] + gColB[col + 2];
        r.w = v.w * gColA[col + 3] + gColB[col + 3];
        ((float4*)out)[idx] = r;
    }
}

// ---------------------------------------------------------------------------
extern "C" void kernel_launch(void* const* d_in, const int* in_sizes, int n_in,
                              void* d_out, int out_size)
{
    const float* query = (const float*)d_in[0];
    const float* key   = (const float*)d_in[1];
    const float* Wq    = (const float*)d_in[2];
    const float* Wk    = (const float*)d_in[3];
    const float* Wv    = (const float*)d_in[4];
    const float* gamma = (const float*)d_in[5];
    const float* beta  = (const float*)d_in[6];
    float* out = (float*)d_out;

    conv_all<<<4864, 256>>>(query, key, Wq, Wk, Wv);

    const int gemm_smem = 6 * GSTG * 2;      // 98304 B
    cudaFuncSetAttribute(gemm_mma, cudaFuncAttributeMaxDynamicSharedMemorySize,
                         gemm_smem);
    dim3 gg(DM / 128, MROWS / 128, 3);
    gemm_mma<<<gg, 256, gemm_smem>>>();

    const int attn_smem = 24576 * 2;         // 49152 B
    cudaFuncSetAttribute(attn_mma, cudaFuncAttributeMaxDynamicSharedMemorySize,
                         attn_smem);
    dim3 ga(LQL / 128, HH, NB);
    attn_mma<<<ga, 128, attn_smem>>>(query);

    colstats_final<<<DM / 32, 256>>>(gamma, beta);

    const int total_f4 = MROWS * DM / 4;     // 2,097,152
    normalize_kernel<<<total_f4 / 1024, 256>>>(out);
}

// round 14
// speedup vs baseline: 1.0735x; 1.0417x over previous
#include <cuda_runtime.h>
#include <cuda_fp16.h>
#include <math.h>
#include <stdint.h>

// Problem constants (fixed shapes)
#define NB   4
#define LQL  2048
#define DM   1024
#define HH   16
#define PP   64
#define MROWS (NB*LQL)        // 8192
#define EPSBN 1e-5f

// ---------------- scratch (device globals: allocation-free) ----------------
__device__ __half gQh [MROWS * DM];   // fp16 Q projection (PRE-SCALED by log2e/32)
__device__ __half gKh [MROWS * DM];
__device__ __half gVh [MROWS * DM];
__device__ __half gAQh[MROWS * DM];
__device__ __half gAKh[MROWS * DM];
__device__ __half gWh [3 * DM * DM];
__device__ float  gRes[MROWS * DM];
__device__ float  gPartS[64 * DM];
__device__ float  gPartQ[64 * DM];
__device__ float  gColA[DM];
__device__ float  gColB[DM];

// ---------------- helpers ----------------
static __device__ __forceinline__ uint32_t smem_u32(const void* p) {
    uint32_t r;
    asm("{ .reg .u64 t; cvta.to.shared.u64 t, %1; cvt.u32.u64 %0, t; }"
        : "=r"(r) : "l"(p));
    return r;
}
static __device__ __forceinline__ void mma_f16(float* d, const uint32_t* a,
                                               uint32_t b0, uint32_t b1)
{
    asm volatile(
        "mma.sync.aligned.m16n8k16.row.col.f32.f16.f16.f32 "
        "{%0,%1,%2,%3}, {%4,%5,%6,%7}, {%8,%9}, {%0,%1,%2,%3};"
        : "+f"(d[0]), "+f"(d[1]), "+f"(d[2]), "+f"(d[3])
        : "r"(a[0]), "r"(a[1]), "r"(a[2]), "r"(a[3]), "r"(b0), "r"(b1));
}
static __device__ __forceinline__ void ldsm_x4(uint32_t* r, uint32_t addr) {
    asm volatile("ldmatrix.sync.aligned.m8n8.x4.shared.b16 {%0,%1,%2,%3}, [%4];"
                 : "=r"(r[0]), "=r"(r[1]), "=r"(r[2]), "=r"(r[3]) : "r"(addr));
}
static __device__ __forceinline__ void ldsm_x2_t(uint32_t& r0, uint32_t& r1,
                                                 uint32_t addr)
{
    asm volatile("ldmatrix.sync.aligned.m8n8.x2.trans.shared.b16 {%0,%1}, [%2];"
                 : "=r"(r0), "=r"(r1) : "r"(addr));
}
static __device__ __forceinline__ float ex2f(float x) {
    float r;
    asm("ex2.approx.f32 %0, %1;" : "=f"(r) : "f"(x));
    return r;
}
static __device__ __forceinline__ uint32_t ex2h2(uint32_t x) {
    uint32_t r;
    asm("ex2.approx.f16x2 %0, %1;" : "=r"(r) : "r"(x));
    return r;
}
#define SWH(r, hc) (((r) << 6) + (((hc) & 7) | ((((hc) >> 3) ^ ((r) & 7)) << 3)))

// ============================================================================
// fused f32 -> f16 conversion pre-pass: 4 float4 per thread for BW
// ============================================================================
__global__ void __launch_bounds__(256) conv_all(const float* __restrict__ q,
                                                const float* __restrict__ k,
                                                const float* __restrict__ wq,
                                                const float* __restrict__ wk,
                                                const float* __restrict__ wv)
{
    const int b = blockIdx.x;
    const float* in;
    __half* out;
    int base;
    if (b < 2048)      { in = q;  out = gAQh;              base = b * 1024; }
    else if (b < 4096) { in = k;  out = gAKh;              base = (b - 2048) * 1024; }
    else if (b < 4352) { in = wq; out = gWh;               base = (b - 4096) * 1024; }
    else if (b < 4608) { in = wk; out = gWh + DM * DM;     base = (b - 4352) * 1024; }
    else               { in = wv; out = gWh + 2 * DM * DM; base = (b - 4608) * 1024; }
    #pragma unroll
    for (int j = 0; j < 4; ++j) {
        int i = base + j * 256 + threadIdx.x;
        float4 v = ((const float4*)in)[i];
        __half2* o = (__half2*)out + 2 * (size_t)i;
        o[0] = __floats2half2_rn(v.x, v.y);
        o[1] = __floats2half2_rn(v.z, v.w);
    }
}

// ============================================================================
// fp16 mma.sync GEMM NT, 3-stage cp.async pipeline.
// z==0 (Q) epilogue pre-scales by (1/32)*log2(e) in fp32 before fp16 store.
// ============================================================================
#define GSTG 8192   // halves per stage per matrix

__global__ void __launch_bounds__(256) gemm_mma()
{
    extern __shared__ __align__(16) __half smh[];
    const int tid  = threadIdx.x;
    const int lane = tid & 31;
    const int wid  = tid >> 5;
    const int g    = lane >> 2;
    const int tg   = lane & 3;
    const int wM   = wid >> 2;
    const int wN   = wid & 3;
    const int n0   = blockIdx.x * 128;
    const int m0   = blockIdx.y * 128;
    const int z    = blockIdx.z;

    const __half* __restrict__ A = (z == 0) ? gAQh : gAKh;
    const __half* __restrict__ W = gWh + (size_t)z * DM * DM;
    __half* __restrict__ C = (z == 0) ? gQh : ((z == 1) ? gKh : gVh);

    uint32_t asA[3], asB[3];
    #pragma unroll
    for (int i = 0; i < 3; ++i) {
        asA[i] = smem_u32(smh + i * GSTG);
        asB[i] = smem_u32(smh + (3 + i) * GSTG);
    }

    float acc[4][4][4] = {};

    const int lr  = tid >> 3;
    const int lc8 = tid & 7;
    const int arow = lane & 15;
    const int asel = lane >> 4;
    const int quad = lane >> 3;
    const int brow = ((quad >> 1) << 3) + (lane & 7);
    const int bsel = quad & 1;

    #pragma unroll
    for (int ps = 0; ps < 2; ++ps) {
        const int k0 = ps * 64;
        #pragma unroll
        for (int it = 0; it < 4; ++it) {
            int r = lr + it * 32;
            uint32_t off = (uint32_t)(r * 128 + ((lc8 ^ (r & 7)) << 4));
            const __half* sa = A + (size_t)(m0 + r) * DM + k0 + lc8 * 8;
            asm volatile("cp.async.cg.shared.global [%0], [%1], 16;"
                         :: "r"(asA[ps] + off), "l"(sa));
            const __half* sb = W + (size_t)(n0 + r) * DM + k0 + lc8 * 8;
            asm volatile("cp.async.cg.shared.global [%0], [%1], 16;"
                         :: "r"(asB[ps] + off), "l"(sb));
        }
        asm volatile("cp.async.commit_group;" ::: "memory");
    }

    const int NSTAGE = DM / 64;   // 16
    int buf = 0, wbuf = 2;
    for (int s = 0; s < NSTAGE; ++s) {
        if (s + 2 < NSTAGE) {
            asm volatile("cp.async.wait_group %0;" :: "n"(1) : "memory");
        } else {
            asm volatile("cp.async.wait_group %0;" :: "n"(0) : "memory");
        }
        __syncthreads();

        if (s + 2 < NSTAGE) {
            const int k0 = (s + 2) * 64;
            #pragma unroll
            for (int it = 0; it < 4; ++it) {
                int r = lr + it * 32;
                uint32_t off = (uint32_t)(r * 128 + ((lc8 ^ (r & 7)) << 4));
                const __half* sa = A + (size_t)(m0 + r) * DM + k0 + lc8 * 8;
                asm volatile("cp.async.cg.shared.global [%0], [%1], 16;"
                             :: "r"(asA[wbuf] + off), "l"(sa));
                const __half* sb = W + (size_t)(n0 + r) * DM + k0 + lc8 * 8;
                asm volatile("cp.async.cg.shared.global [%0], [%1], 16;"
                             :: "r"(asB[wbuf] + off), "l"(sb));
            }
            asm volatile("cp.async.commit_group;" ::: "memory");
        }

        #pragma unroll
        for (int kk = 0; kk < 4; ++kk) {
            uint32_t af[4][4];
            const uint32_t ckA = (uint32_t)(2 * kk + asel);
            #pragma unroll
            for (int mt = 0; mt < 4; ++mt) {
                int row = wM * 64 + mt * 16 + arow;
                uint32_t addr = asA[buf] + (uint32_t)(row * 128)
                              + ((ckA ^ (uint32_t)(row & 7)) << 4);
                ldsm_x4(af[mt], addr);
            }
            uint32_t bf[4][2];
            const uint32_t ckB = (uint32_t)(2 * kk + bsel);
            #pragma unroll
            for (int np = 0; np < 2; ++np) {
                int row = wN * 32 + np * 16 + brow;
                uint32_t addr = asB[buf] + (uint32_t)(row * 128)
                              + ((ckB ^ (uint32_t)(row & 7)) << 4);
                uint32_t t[4];
                ldsm_x4(t, addr);
                bf[2 * np][0] = t[0]; bf[2 * np][1] = t[1];
                bf[2 * np + 1][0] = t[2]; bf[2 * np + 1][1] = t[3];
            }
            #pragma unroll
            for (int mt = 0; mt < 4; ++mt)
                #pragma unroll
                for (int nt = 0; nt < 4; ++nt)
                    mma_f16(acc[mt][nt], af[mt], bf[nt][0], bf[nt][1]);
        }
        buf = (buf + 1) % 3;
        wbuf = (wbuf + 1) % 3;
    }

    const float cs = (z == 0) ? 0.045084222f : 1.0f;   // 0.03125*log2(e)
    #pragma unroll
    for (int mt = 0; mt < 4; ++mt) {
        int row = m0 + wM * 64 + mt * 16 + g;
        #pragma unroll
        for (int nt = 0; nt < 4; ++nt) {
            int col = n0 + wN * 32 + nt * 8 + tg * 2;
            *(__half2*)(C + (size_t)row * DM + col) =
                __floats2half2_rn(acc[mt][nt][0] * cs, acc[mt][nt][1] * cs);
            *(__half2*)(C + (size_t)(row + 8) * DM + col) =
                __floats2half2_rn(acc[mt][nt][2] * cs, acc[mt][nt][3] * cs);
        }
    }
}

// ============================================================================
// fp16 mma.sync causal flash attention + fused BN partial stats.
// Q lives in its own smem buffer (Qs); Q fragments re-loaded per K-tile via
// ldmatrix -> 32 fewer persistent registers -> 3 CTAs/SM without spills.
// Smem: K0,V0,K1,V1 (32KB) + Ss/P (16KB) + Qs (16KB) = 64KB.
// ============================================================================
__global__ void __launch_bounds__(128, 3) attn_mma(const float* __restrict__ query)
{
    extern __shared__ __align__(16) __half ash[];
    __half* Kb[2] = { ash,         ash + 8192 };
    __half* Vb[2] = { ash + 4096,  ash + 12288 };
    __half* Ss    = ash + 16384;                 // P staging (128 x 64 halves)
    __half* Qs    = ash + 24576;                 // Q tile    (128 x 64 halves)
    const uint32_t sK[2] = { smem_u32(Kb[0]), smem_u32(Kb[1]) };
    const uint32_t sV[2] = { smem_u32(Vb[0]), smem_u32(Vb[1]) };
    const uint32_t sS    = smem_u32(Ss);
    const uint32_t sQ    = smem_u32(Qs);

    const int tid  = threadIdx.x;
    const int lane = tid & 31;
    const int wid  = tid >> 5;
    const int g    = lane >> 2;
    const int tg   = lane & 3;
    const int qt   = (int)(gridDim.x - 1) - (int)blockIdx.x;  // heavy-first
    const int h    = blockIdx.y;
    const int n    = blockIdx.z;

    const size_t nbase = (size_t)n * LQL * DM;
    const int hcol = h * PP;
    const int KT = 2 * qt + 2;

    const int arow = lane & 15;
    const int asel = lane >> 4;
    const int quad = lane >> 3;
    const int brow = ((quad >> 1) << 3) + (lane & 7);
    const int bsel = quad & 1;

    // ---- prefetch K/V tile 0 + stage Q via cp.async (all overlapped) ----
    {
        const __half* Kg = gKh + nbase + hcol;
        const __half* Vg = gVh + nbase + hcol;
        #pragma unroll
        for (int i = 0; i < 4; ++i) {
            int idx = tid + i * 128;
            int r = idx >> 3, c8 = idx & 7;
            uint32_t off = (uint32_t)(r * 128 + ((c8 ^ (r & 7)) << 4));
            asm volatile("cp.async.cg.shared.global [%0], [%1], 16;"
                         :: "r"(sK[0] + off), "l"(Kg + (size_t)r * DM + c8 * 8));
            asm volatile("cp.async.cg.shared.global [%0], [%1], 16;"
                         :: "r"(sV[0] + off), "l"(Vg + (size_t)r * DM + c8 * 8));
        }
        const __half* Qg = gQh + nbase + (size_t)qt * 128 * DM + hcol;
        #pragma unroll
        for (int i = 0; i < 8; ++i) {
            int idx = tid + i * 128;
            int r = idx >> 3, c8 = idx & 7;
            uint32_t off = (uint32_t)(r * 128 + ((c8 ^ (r & 7)) << 4));
            asm volatile("cp.async.cg.shared.global [%0], [%1], 16;"
                         :: "r"(sQ + off), "l"(Qg + (size_t)r * DM + c8 * 8));
        }
        asm volatile("cp.async.commit_group;" ::: "memory");
    }
    asm volatile("cp.async.wait_group %0;" :: "n"(0) : "memory");
    __syncthreads();

    float o[2][8][4] = {};
    float mrow[2][2], lrow[2][2];
    #pragma unroll
    for (int a = 0; a < 2; ++a)
        #pragma unroll
        for (int b = 0; b < 2; ++b) { mrow[a][b] = -INFINITY; lrow[a][b] = 0.f; }

    for (int kt = 0; kt < KT; ++kt) {
        const int buf = kt & 1;
        if (kt + 1 < KT) {
            const __half* Kg = gKh + nbase + (size_t)(kt + 1) * 64 * DM + hcol;
            const __half* Vg = gVh + nbase + (size_t)(kt + 1) * 64 * DM + hcol;
            #pragma unroll
            for (int i = 0; i < 4; ++i) {
                int idx = tid + i * 128;
                int r = idx >> 3, c8 = idx & 7;
                uint32_t off = (uint32_t)(r * 128 + ((c8 ^ (r & 7)) << 4));
                asm volatile("cp.async.cg.shared.global [%0], [%1], 16;"
                             :: "r"(sK[buf ^ 1] + off), "l"(Kg + (size_t)r * DM + c8 * 8));
                asm volatile("cp.async.cg.shared.global [%0], [%1], 16;"
                             :: "r"(sV[buf ^ 1] + off), "l"(Vg + (size_t)r * DM + c8 * 8));
            }
            asm volatile("cp.async.commit_group;" ::: "memory");
            asm volatile("cp.async.wait_group %0;" :: "n"(1) : "memory");
        } else {
            asm volatile("cp.async.wait_group %0;" :: "n"(0) : "memory");
        }
        __syncthreads();

        // ---- S = Q K^T (Q frags re-loaded from Qs via ldmatrix) ----
        float s[2][8][4] = {};
        #pragma unroll
        for (int ks = 0; ks < 4; ++ks) {
            uint32_t qf0[4], qf1[4];
            {
                const uint32_t ckQ = (uint32_t)(2 * ks + asel);
                int row0 = wid * 32 + arow;
                int row1 = wid * 32 + 16 + arow;
                ldsm_x4(qf0, sQ + (uint32_t)(row0 * 128)
                             + ((ckQ ^ (uint32_t)(row0 & 7)) << 4));
                ldsm_x4(qf1, sQ + (uint32_t)(row1 * 128)
                             + ((ckQ ^ (uint32_t)(row1 & 7)) << 4));
            }
            const uint32_t ck = (uint32_t)(2 * ks + bsel);
            #pragma unroll
            for (int nbp = 0; nbp < 4; ++nbp) {
                int row = nbp * 16 + brow;
                uint32_t addr = sK[buf] + (uint32_t)(row * 128)
                              + ((ck ^ (uint32_t)(row & 7)) << 4);
                uint32_t t[4];
                ldsm_x4(t, addr);
                mma_f16(s[0][2 * nbp],     qf0, t[0], t[1]);
                mma_f16(s[1][2 * nbp],     qf1, t[0], t[1]);
                mma_f16(s[0][2 * nbp + 1], qf0, t[2], t[3]);
                mma_f16(s[1][2 * nbp + 1], qf1, t[2], t[3]);
            }
        }

        // ---- mask + online softmax (f16x2 ex2, P stored inline) ----
        const bool tail = (kt >= 2 * qt);
        #pragma unroll
        for (int mb = 0; mb < 2; ++mb) {
            #pragma unroll
            for (int rr = 0; rr < 2; ++rr) {
                const int rloc = wid * 32 + mb * 16 + rr * 8 + g;
                const int grow = qt * 128 + rloc;
                float tm = -INFINITY;
                #pragma unroll
                for (int nb = 0; nb < 8; ++nb) {
                    float v0 = s[mb][nb][rr * 2 + 0];
                    float v1 = s[mb][nb][rr * 2 + 1];
                    if (tail) {
                        int c0 = kt * 64 + nb * 8 + tg * 2;
                        if (c0     > grow) v0 = -1e30f;
                        if (c0 + 1 > grow) v1 = -1e30f;
                    }
                    s[mb][nb][rr * 2 + 0] = v0;
                    s[mb][nb][rr * 2 + 1] = v1;
                    tm = fmaxf(tm, fmaxf(v0, v1));
                }
                tm = fmaxf(tm, __shfl_xor_sync(0xffffffffu, tm, 1));
                tm = fmaxf(tm, __shfl_xor_sync(0xffffffffu, tm, 2));
                float nm   = fmaxf(mrow[mb][rr], tm);
                float corr = ex2f(mrow[mb][rr] - nm);
                mrow[mb][rr] = nm;
                float rs = 0.f;
                #pragma unroll
                for (int nb = 0; nb < 8; ++nb) {
                    __half2 a2 = __floats2half2_rn(s[mb][nb][rr * 2 + 0] - nm,
                                                   s[mb][nb][rr * 2 + 1] - nm);
                    uint32_t p2 = ex2h2(*(uint32_t*)&a2);
                    *(uint32_t*)(Ss + SWH(rloc, nb * 8 + 2 * tg)) = p2;
                    float2 pf = __half22float2(*(__half2*)&p2);
                    rs += pf.x + pf.y;
                }
                rs += __shfl_xor_sync(0xffffffffu, rs, 1);
                rs += __shfl_xor_sync(0xffffffffu, rs, 2);
                lrow[mb][rr] = lrow[mb][rr] * corr + rs;
                #pragma unroll
                for (int nb = 0; nb < 8; ++nb) {
                    o[mb][nb][rr * 2 + 0] *= corr;
                    o[mb][nb][rr * 2 + 1] *= corr;
                }
            }
        }

        // ---- O += P V (P A-frags via ldmatrix, V via ldmatrix.trans) ----
        #pragma unroll
        for (int ks = 0; ks < 4; ++ks) {
            uint32_t af[2][4];
            const uint32_t ckP = (uint32_t)(2 * ks + asel);
            #pragma unroll
            for (int mb = 0; mb < 2; ++mb) {
                int row = wid * 32 + mb * 16 + arow;
                uint32_t addr = sS + (uint32_t)(row * 128)
                              + ((ckP ^ (uint32_t)(row & 7)) << 4);
                ldsm_x4(af[mb], addr);
            }
            const int vrow = ks * 16 + (lane & 15);
            const uint32_t rowbase = sV[buf] + (uint32_t)vrow * 128u;
            const uint32_t rx = (uint32_t)(vrow & 7) << 4;
            #pragma unroll
            for (int nb = 0; nb < 8; ++nb) {
                uint32_t addr = rowbase + (((uint32_t)nb << 4) ^ rx);
                uint32_t b0, b1;
                ldsm_x2_t(b0, b1, addr);
                mma_f16(o[0][nb], af[0], b0, b1);
                mma_f16(o[1][nb], af[1], b0, b1);
            }
        }
        __syncthreads();
    }

    // ---- epilogue: normalize, residual add, write gRes, fused col stats ----
    float colS[16], colQ[16];
    #pragma unroll
    for (int i = 0; i < 16; ++i) { colS[i] = 0.f; colQ[i] = 0.f; }

    #pragma unroll
    for (int mb = 0; mb < 2; ++mb) {
        #pragma unroll
        for (int rr = 0; rr < 2; ++rr) {
            float inv = 1.0f / lrow[mb][rr];
            int grow = qt * 128 + wid * 32 + mb * 16 + rr * 8 + g;
            size_t rowoff = nbase + (size_t)grow * DM + hcol;
            #pragma unroll
            for (int nb = 0; nb < 8; ++nb) {
                int c = nb * 8 + tg * 2;
                float2 qv = *(const float2*)(query + rowoff + c);
                float2 w;
                w.x = o[mb][nb][rr * 2 + 0] * inv + qv.x;
                w.y = o[mb][nb][rr * 2 + 1] * inv + qv.y;
                *(float2*)(gRes + rowoff + c) = w;
                colS[2 * nb]     += w.x;
                colQ[2 * nb]     += w.x * w.x;
                colS[2 * nb + 1] += w.y;
                colQ[2 * nb + 1] += w.y * w.y;
            }
        }
    }
    #pragma unroll
    for (int i = 0; i < 16; ++i) {
        #pragma unroll
        for (int off = 4; off < 32; off <<= 1) {
            colS[i] += __shfl_xor_sync(0xffffffffu, colS[i], off);
            colQ[i] += __shfl_xor_sync(0xffffffffu, colQ[i], off);
        }
    }
    float* redS = (float*)ash;          // [4][64]
    float* redQ = redS + 256;           // [4][64]
    if (g == 0) {
        #pragma unroll
        for (int i = 0; i < 16; ++i) {
            int c = (i >> 1) * 8 + tg * 2 + (i & 1);
            redS[wid * 64 + c] = colS[i];
            redQ[wid * 64 + c] = colQ[i];
        }
    }
    __syncthreads();
    if (tid < 64) {
        float s = redS[tid] + redS[64 + tid] + redS[128 + tid] + redS[192 + tid];
        float q = redQ[tid] + redQ[64 + tid] + redQ[128 + tid] + redQ[192 + tid];
        int chunk = n * 16 + qt;
        gPartS[chunk * DM + hcol + tid] = s;
        gPartQ[chunk * DM + hcol + tid] = q;
    }
}

// ---------------------------------------------------------------------------
// BatchNorm: final stats + fused normalize
// ---------------------------------------------------------------------------
__global__ void __launch_bounds__(256) colstats_final(const float* __restrict__ gamma,
                                                      const float* __restrict__ beta)
{
    const int cidx = threadIdx.x & 31;
    const int seg  = threadIdx.x >> 5;
    const int col  = blockIdx.x * 32 + cidx;
    float s = 0.f, q = 0.f;
    #pragma unroll
    for (int c = 0; c < 8; ++c) {
        int chunk = seg * 8 + c;
        s += gPartS[chunk * DM + col];
        q += gPartQ[chunk * DM + col];
    }
    __shared__ float shS[8][33], shQ[8][33];
    shS[seg][cidx] = s;
    shQ[seg][cidx] = q;
    __syncthreads();
    if (seg == 0) {
        float ts = 0.f, tq = 0.f;
        #pragma unroll
        for (int i = 0; i < 8; ++i) { ts += shS[i][cidx]; tq += shQ[i][cidx]; }
        const float invn = 1.0f / (float)MROWS;
        float mean = ts * invn;
        float var  = tq * invn - mean * mean;
        float inv  = rsqrtf(var + EPSBN);
        float a    = gamma[col] * inv;
        gColA[col] = a;
        gColB[col] = beta[col] - mean * a;
    }
}

// 4 float4 per thread: fewer blocks, more ILP on a pure-BW kernel
__global__ void __launch_bounds__(256) normalize_kernel(float* __restrict__ out)
{
    const size_t base = (size_t)blockIdx.x * 1024 + threadIdx.x;
    #pragma unroll
    for (int j = 0; j < 4; ++j) {
        const size_t idx = base + j * 256;
        float4 v = ((const float4*)gRes)[idx];
        int col = (int)((idx * 4) & (DM - 1));
        float4 r;
        r.x = v.x * gColA[col + 0] + gColB[col + 0];
        r.y = v.y * gColA[col + 1] + gColB[col + 1];
        r.z = v.z * gColA[col + 2] + gColB[col + 2];
        r.w = v.w * gColA[col + 3] + gColB[col + 3];
        ((float4*)out)[idx] = r;
    }
}

// ---------------------------------------------------------------------------
extern "C" void kernel_launch(void* const* d_in, const int* in_sizes, int n_in,
                              void* d_out, int out_size)
{
    const float* query = (const float*)d_in[0];
    const float* key   = (const float*)d_in[1];
    const float* Wq    = (const float*)d_in[2];
    const float* Wk    = (const float*)d_in[3];
    const float* Wv    = (const float*)d_in[4];
    const float* gamma = (const float*)d_in[5];
    const float* beta  = (const float*)d_in[6];
    float* out = (float*)d_out;

    conv_all<<<4864, 256>>>(query, key, Wq, Wk, Wv);

    const int gemm_smem = 6 * GSTG * 2;      // 98304 B
    cudaFuncSetAttribute(gemm_mma, cudaFuncAttributeMaxDynamicSharedMemorySize,
                         gemm_smem);
    dim3 gg(DM / 128, MROWS / 128, 3);
    gemm_mma<<<gg, 256, gemm_smem>>>();

    const int attn_smem = 32768 * 2;         // 65536 B (K/V + P + Q)
    cudaFuncSetAttribute(attn_mma, cudaFuncAttributeMaxDynamicSharedMemorySize,
                         attn_smem);
    dim3 ga(LQL / 128, HH, NB);
    attn_mma<<<ga, 128, attn_smem>>>(query);

    colstats_final<<<DM / 32, 256>>>(gamma, beta);

    const int total_f4 = MROWS * DM / 4;     // 2,097,152
    normalize_kernel<<<total_f4 / 1024, 256>>>(out);
}

// round 15
// speedup vs baseline: 1.0881x; 1.0136x over previous
#include <cuda_runtime.h>
#include <cuda_fp16.h>
#include <math.h>
#include <stdint.h>

// Problem constants (fixed shapes)
#define NB   4
#define LQL  2048
#define DM   1024
#define HH   16
#define PP   64
#define MROWS (NB*LQL)        // 8192
#define EPSBN 1e-5f

// ---------------- scratch (device globals: allocation-free) ----------------
__device__ __half gQh [MROWS * DM];   // fp16 Q projection (PRE-SCALED by log2e/32)
__device__ __half gKh [MROWS * DM];
__device__ __half gVh [MROWS * DM];
__device__ __half gAQh[MROWS * DM];
__device__ __half gAKh[MROWS * DM];
__device__ __half gWh [3 * DM * DM];
__device__ float  gRes[MROWS * DM];
__device__ float  gPartS[64 * DM];
__device__ float  gPartQ[64 * DM];
__device__ float  gColA[DM];
__device__ float  gColB[DM];

// ---------------- helpers ----------------
static __device__ __forceinline__ uint32_t smem_u32(const void* p) {
    uint32_t r;
    asm("{ .reg .u64 t; cvta.to.shared.u64 t, %1; cvt.u32.u64 %0, t; }"
        : "=r"(r) : "l"(p));
    return r;
}
static __device__ __forceinline__ void mma_f16(float* d, const uint32_t* a,
                                               uint32_t b0, uint32_t b1)
{
    asm volatile(
        "mma.sync.aligned.m16n8k16.row.col.f32.f16.f16.f32 "
        "{%0,%1,%2,%3}, {%4,%5,%6,%7}, {%8,%9}, {%0,%1,%2,%3};"
        : "+f"(d[0]), "+f"(d[1]), "+f"(d[2]), "+f"(d[3])
        : "r"(a[0]), "r"(a[1]), "r"(a[2]), "r"(a[3]), "r"(b0), "r"(b1));
}
static __device__ __forceinline__ void ldsm_x4(uint32_t* r, uint32_t addr) {
    asm volatile("ldmatrix.sync.aligned.m8n8.x4.shared.b16 {%0,%1,%2,%3}, [%4];"
                 : "=r"(r[0]), "=r"(r[1]), "=r"(r[2]), "=r"(r[3]) : "r"(addr));
}
static __device__ __forceinline__ void ldsm_x2_t(uint32_t& r0, uint32_t& r1,
                                                 uint32_t addr)
{
    asm volatile("ldmatrix.sync.aligned.m8n8.x2.trans.shared.b16 {%0,%1}, [%2];"
                 : "=r"(r0), "=r"(r1) : "r"(addr));
}
static __device__ __forceinline__ void ldsm_x4_t(uint32_t* r, uint32_t addr) {
    asm volatile("ldmatrix.sync.aligned.m8n8.x4.trans.shared.b16 {%0,%1,%2,%3}, [%4];"
                 : "=r"(r[0]), "=r"(r[1]), "=r"(r[2]), "=r"(r[3]) : "r"(addr));
}
static __device__ __forceinline__ float ex2f(float x) {
    float r;
    asm("ex2.approx.f32 %0, %1;" : "=f"(r) : "f"(x));
    return r;
}
static __device__ __forceinline__ uint32_t ex2h2(uint32_t x) {
    uint32_t r;
    asm("ex2.approx.f16x2 %0, %1;" : "=r"(r) : "r"(x));
    return r;
}
#define SWH(r, hc) (((r) << 6) + (((hc) & 7) | ((((hc) >> 3) ^ ((r) & 7)) << 3)))

// ============================================================================
// fused f32 -> f16 conversion pre-pass: 4 float4 per thread for BW
// ============================================================================
__global__ void __launch_bounds__(256) conv_all(const float* __restrict__ q,
                                                const float* __restrict__ k,
                                                const float* __restrict__ wq,
                                                const float* __restrict__ wk,
                                                const float* __restrict__ wv)
{
    const int b = blockIdx.x;
    const float* in;
    __half* out;
    int base;
    if (b < 2048)      { in = q;  out = gAQh;              base = b * 1024; }
    else if (b < 4096) { in = k;  out = gAKh;              base = (b - 2048) * 1024; }
    else if (b < 4352) { in = wq; out = gWh;               base = (b - 4096) * 1024; }
    else if (b < 4608) { in = wk; out = gWh + DM * DM;     base = (b - 4352) * 1024; }
    else               { in = wv; out = gWh + 2 * DM * DM; base = (b - 4608) * 1024; }
    #pragma unroll
    for (int j = 0; j < 4; ++j) {
        int i = base + j * 256 + threadIdx.x;
        float4 v = ((const float4*)in)[i];
        __half2* o = (__half2*)out + 2 * (size_t)i;
        o[0] = __floats2half2_rn(v.x, v.y);
        o[1] = __floats2half2_rn(v.z, v.w);
    }
}

// ============================================================================
// fp16 mma.sync GEMM NT, 3-stage cp.async pipeline. (unchanged from R14)
// ============================================================================
#define GSTG 8192   // halves per stage per matrix

__global__ void __launch_bounds__(256) gemm_mma()
{
    extern __shared__ __align__(16) __half smh[];
    const int tid  = threadIdx.x;
    const int lane = tid & 31;
    const int wid  = tid >> 5;
    const int g    = lane >> 2;
    const int tg   = lane & 3;
    const int wM   = wid >> 2;
    const int wN   = wid & 3;
    const int n0   = blockIdx.x * 128;
    const int m0   = blockIdx.y * 128;
    const int z    = blockIdx.z;

    const __half* __restrict__ A = (z == 0) ? gAQh : gAKh;
    const __half* __restrict__ W = gWh + (size_t)z * DM * DM;
    __half* __restrict__ C = (z == 0) ? gQh : ((z == 1) ? gKh : gVh);

    uint32_t asA[3], asB[3];
    #pragma unroll
    for (int i = 0; i < 3; ++i) {
        asA[i] = smem_u32(smh + i * GSTG);
        asB[i] = smem_u32(smh + (3 + i) * GSTG);
    }

    float acc[4][4][4] = {};

    const int lr  = tid >> 3;
    const int lc8 = tid & 7;
    const int arow = lane & 15;
    const int asel = lane >> 4;
    const int quad = lane >> 3;
    const int brow = ((quad >> 1) << 3) + (lane & 7);
    const int bsel = quad & 1;

    #pragma unroll
    for (int ps = 0; ps < 2; ++ps) {
        const int k0 = ps * 64;
        #pragma unroll
        for (int it = 0; it < 4; ++it) {
            int r = lr + it * 32;
            uint32_t off = (uint32_t)(r * 128 + ((lc8 ^ (r & 7)) << 4));
            const __half* sa = A + (size_t)(m0 + r) * DM + k0 + lc8 * 8;
            asm volatile("cp.async.cg.shared.global [%0], [%1], 16;"
                         :: "r"(asA[ps] + off), "l"(sa));
            const __half* sb = W + (size_t)(n0 + r) * DM + k0 + lc8 * 8;
            asm volatile("cp.async.cg.shared.global [%0], [%1], 16;"
                         :: "r"(asB[ps] + off), "l"(sb));
        }
        asm volatile("cp.async.commit_group;" ::: "memory");
    }

    const int NSTAGE = DM / 64;   // 16
    int buf = 0, wbuf = 2;
    for (int s = 0; s < NSTAGE; ++s) {
        if (s + 2 < NSTAGE) {
            asm volatile("cp.async.wait_group %0;" :: "n"(1) : "memory");
        } else {
            asm volatile("cp.async.wait_group %0;" :: "n"(0) : "memory");
        }
        __syncthreads();

        if (s + 2 < NSTAGE) {
            const int k0 = (s + 2) * 64;
            #pragma unroll
            for (int it = 0; it < 4; ++it) {
                int r = lr + it * 32;
                uint32_t off = (uint32_t)(r * 128 + ((lc8 ^ (r & 7)) << 4));
                const __half* sa = A + (size_t)(m0 + r) * DM + k0 + lc8 * 8;
                asm volatile("cp.async.cg.shared.global [%0], [%1], 16;"
                             :: "r"(asA[wbuf] + off), "l"(sa));
                const __half* sb = W + (size_t)(n0 + r) * DM + k0 + lc8 * 8;
                asm volatile("cp.async.cg.shared.global [%0], [%1], 16;"
                             :: "r"(asB[wbuf] + off), "l"(sb));
            }
            asm volatile("cp.async.commit_group;" ::: "memory");
        }

        #pragma unroll
        for (int kk = 0; kk < 4; ++kk) {
            uint32_t af[4][4];
            const uint32_t ckA = (uint32_t)(2 * kk + asel);
            #pragma unroll
            for (int mt = 0; mt < 4; ++mt) {
                int row = wM * 64 + mt * 16 + arow;
                uint32_t addr = asA[buf] + (uint32_t)(row * 128)
                              + ((ckA ^ (uint32_t)(row & 7)) << 4);
                ldsm_x4(af[mt], addr);
            }
            uint32_t bf[4][2];
            const uint32_t ckB = (uint32_t)(2 * kk + bsel);
            #pragma unroll
            for (int np = 0; np < 2; ++np) {
                int row = wN * 32 + np * 16 + brow;
                uint32_t addr = asB[buf] + (uint32_t)(row * 128)
                              + ((ckB ^ (uint32_t)(row & 7)) << 4);
                uint32_t t[4];
                ldsm_x4(t, addr);
                bf[2 * np][0] = t[0]; bf[2 * np][1] = t[1];
                bf[2 * np + 1][0] = t[2]; bf[2 * np + 1][1] = t[3];
            }
            #pragma unroll
            for (int mt = 0; mt < 4; ++mt)
                #pragma unroll
                for (int nt = 0; nt < 4; ++nt)
                    mma_f16(acc[mt][nt], af[mt], bf[nt][0], bf[nt][1]);
        }
        buf = (buf + 1) % 3;
        wbuf = (wbuf + 1) % 3;
    }

    const float cs = (z == 0) ? 0.045084222f : 1.0f;   // 0.03125*log2(e)
    #pragma unroll
    for (int mt = 0; mt < 4; ++mt) {
        int row = m0 + wM * 64 + mt * 16 + g;
        #pragma unroll
        for (int nt = 0; nt < 4; ++nt) {
            int col = n0 + wN * 32 + nt * 8 + tg * 2;
            *(__half2*)(C + (size_t)row * DM + col) =
                __floats2half2_rn(acc[mt][nt][0] * cs, acc[mt][nt][1] * cs);
            *(__half2*)(C + (size_t)(row + 8) * DM + col) =
                __floats2half2_rn(acc[mt][nt][2] * cs, acc[mt][nt][3] * cs);
        }
    }
}

// ============================================================================
// fp16 mma.sync causal flash attention + fused BN partial stats.
// Row-sum l accumulated as an extra MMA column (P @ e0) -> no sum shuffles.
// V loads via ldmatrix.x4.trans (half the LDSM). 3 CTAs/SM.
// Smem: K/V dbuf 32KB + Ss 16KB + Qs 16KB + ones 512B.
// ============================================================================
__global__ void __launch_bounds__(128, 3) attn_mma(const float* __restrict__ query)
{
    extern __shared__ __align__(16) __half ash[];
    __half* Kb[2] = { ash,         ash + 8192 };
    __half* Vb[2] = { ash + 4096,  ash + 12288 };
    __half* Ss    = ash + 16384;                 // P staging (128 x 64 halves)
    __half* Qs    = ash + 24576;                 // Q tile    (128 x 64 halves)
    __half* Ones  = ash + 32768;                 // 16 x 8 halves, col0 = 1
    const uint32_t sK[2] = { smem_u32(Kb[0]), smem_u32(Kb[1]) };
    const uint32_t sV[2] = { smem_u32(Vb[0]), smem_u32(Vb[1]) };
    const uint32_t sS    = smem_u32(Ss);
    const uint32_t sQ    = smem_u32(Qs);
    const uint32_t sO    = smem_u32(Ones);

    const int tid  = threadIdx.x;
    const int lane = tid & 31;
    const int wid  = tid >> 5;
    const int g    = lane >> 2;
    const int tg   = lane & 3;
    const int qt   = (int)(gridDim.x - 1) - (int)blockIdx.x;  // heavy-first
    const int h    = blockIdx.y;
    const int n    = blockIdx.z;

    const size_t nbase = (size_t)n * LQL * DM;
    const int hcol = h * PP;
    const int KT = 2 * qt + 2;

    const int arow = lane & 15;
    const int asel = lane >> 4;
    const int quad = lane >> 3;
    const int brow = ((quad >> 1) << 3) + (lane & 7);
    const int bsel = quad & 1;

    // ---- prefetch K/V tile 0 + stage Q via cp.async; init ones tile ----
    {
        const __half* Kg = gKh + nbase + hcol;
        const __half* Vg = gVh + nbase + hcol;
        #pragma unroll
        for (int i = 0; i < 4; ++i) {
            int idx = tid + i * 128;
            int r = idx >> 3, c8 = idx & 7;
            uint32_t off = (uint32_t)(r * 128 + ((c8 ^ (r & 7)) << 4));
            asm volatile("cp.async.cg.shared.global [%0], [%1], 16;"
                         :: "r"(sK[0] + off), "l"(Kg + (size_t)r * DM + c8 * 8));
            asm volatile("cp.async.cg.shared.global [%0], [%1], 16;"
                         :: "r"(sV[0] + off), "l"(Vg + (size_t)r * DM + c8 * 8));
        }
        const __half* Qg = gQh + nbase + (size_t)qt * 128 * DM + hcol;
        #pragma unroll
        for (int i = 0; i < 8; ++i) {
            int idx = tid + i * 128;
            int r = idx >> 3, c8 = idx & 7;
            uint32_t off = (uint32_t)(r * 128 + ((c8 ^ (r & 7)) << 4));
            asm volatile("cp.async.cg.shared.global [%0], [%1], 16;"
                         :: "r"(sQ + off), "l"(Qg + (size_t)r * DM + c8 * 8));
        }
        asm volatile("cp.async.commit_group;" ::: "memory");
        // ones tile: 16 rows x 8 halves, col0=1.0h (pair0 = 0x00003C00)
        if (tid < 64)
            ((uint32_t*)Ones)[tid] = ((tid & 3) == 0) ? 0x00003C00u : 0u;
    }
    asm volatile("cp.async.wait_group %0;" :: "n"(0) : "memory");
    __syncthreads();

    // constant ones B-fragment (k16 x n8, col0 = 1): load once
    uint32_t ones0, ones1;
    ldsm_x2_t(ones0, ones1, sO + (uint32_t)((lane & 15) * 16));

    float o[2][8][4] = {};
    float oL[2][4] = {};                 // l accumulator (P @ e0)
    float mrow[2][2];
    #pragma unroll
    for (int a = 0; a < 2; ++a)
        #pragma unroll
        for (int b = 0; b < 2; ++b) mrow[a][b] = -INFINITY;

    for (int kt = 0; kt < KT; ++kt) {
        const int buf = kt & 1;
        if (kt + 1 < KT) {
            const __half* Kg = gKh + nbase + (size_t)(kt + 1) * 64 * DM + hcol;
            const __half* Vg = gVh + nbase + (size_t)(kt + 1) * 64 * DM + hcol;
            #pragma unroll
            for (int i = 0; i < 4; ++i) {
                int idx = tid + i * 128;
                int r = idx >> 3, c8 = idx & 7;
                uint32_t off = (uint32_t)(r * 128 + ((c8 ^ (r & 7)) << 4));
                asm volatile("cp.async.cg.shared.global [%0], [%1], 16;"
                             :: "r"(sK[buf ^ 1] + off), "l"(Kg + (size_t)r * DM + c8 * 8));
                asm volatile("cp.async.cg.shared.global [%0], [%1], 16;"
                             :: "r"(sV[buf ^ 1] + off), "l"(Vg + (size_t)r * DM + c8 * 8));
            }
            asm volatile("cp.async.commit_group;" ::: "memory");
            asm volatile("cp.async.wait_group %0;" :: "n"(1) : "memory");
        } else {
            asm volatile("cp.async.wait_group %0;" :: "n"(0) : "memory");
        }
        __syncthreads();

        // ---- S = Q K^T (Q frags re-loaded from Qs via ldmatrix) ----
        float s[2][8][4] = {};
        #pragma unroll
        for (int ks = 0; ks < 4; ++ks) {
            uint32_t qf0[4], qf1[4];
            {
                const uint32_t ckQ = (uint32_t)(2 * ks + asel);
                int row0 = wid * 32 + arow;
                int row1 = wid * 32 + 16 + arow;
                ldsm_x4(qf0, sQ + (uint32_t)(row0 * 128)
                             + ((ckQ ^ (uint32_t)(row0 & 7)) << 4));
                ldsm_x4(qf1, sQ + (uint32_t)(row1 * 128)
                             + ((ckQ ^ (uint32_t)(row1 & 7)) << 4));
            }
            const uint32_t ck = (uint32_t)(2 * ks + bsel);
            #pragma unroll
            for (int nbp = 0; nbp < 4; ++nbp) {
                int row = nbp * 16 + brow;
                uint32_t addr = sK[buf] + (uint32_t)(row * 128)
                              + ((ck ^ (uint32_t)(row & 7)) << 4);
                uint32_t t[4];
                ldsm_x4(t, addr);
                mma_f16(s[0][2 * nbp],     qf0, t[0], t[1]);
                mma_f16(s[1][2 * nbp],     qf1, t[0], t[1]);
                mma_f16(s[0][2 * nbp + 1], qf0, t[2], t[3]);
                mma_f16(s[1][2 * nbp + 1], qf1, t[2], t[3]);
            }
        }

        // ---- mask + online softmax (max only; sum rides the PV MMA) ----
        const bool tail = (kt >= 2 * qt);
        #pragma unroll
        for (int mb = 0; mb < 2; ++mb) {
            #pragma unroll
            for (int rr = 0; rr < 2; ++rr) {
                const int rloc = wid * 32 + mb * 16 + rr * 8 + g;
                const int grow = qt * 128 + rloc;
                float tm = -INFINITY;
                #pragma unroll
                for (int nb = 0; nb < 8; ++nb) {
                    float v0 = s[mb][nb][rr * 2 + 0];
                    float v1 = s[mb][nb][rr * 2 + 1];
                    if (tail) {
                        int c0 = kt * 64 + nb * 8 + tg * 2;
                        if (c0     > grow) v0 = -1e30f;
                        if (c0 + 1 > grow) v1 = -1e30f;
                    }
                    s[mb][nb][rr * 2 + 0] = v0;
                    s[mb][nb][rr * 2 + 1] = v1;
                    tm = fmaxf(tm, fmaxf(v0, v1));
                }
                tm = fmaxf(tm, __shfl_xor_sync(0xffffffffu, tm, 1));
                tm = fmaxf(tm, __shfl_xor_sync(0xffffffffu, tm, 2));
                float nm   = fmaxf(mrow[mb][rr], tm);
                float corr = ex2f(mrow[mb][rr] - nm);
                mrow[mb][rr] = nm;
                #pragma unroll
                for (int nb = 0; nb < 8; ++nb) {
                    __half2 a2 = __floats2half2_rn(s[mb][nb][rr * 2 + 0] - nm,
                                                   s[mb][nb][rr * 2 + 1] - nm);
                    uint32_t p2 = ex2h2(*(uint32_t*)&a2);
                    *(uint32_t*)(Ss + SWH(rloc, nb * 8 + 2 * tg)) = p2;
                }
                #pragma unroll
                for (int nb = 0; nb < 8; ++nb) {
                    o[mb][nb][rr * 2 + 0] *= corr;
                    o[mb][nb][rr * 2 + 1] *= corr;
                }
                oL[mb][rr * 2 + 0] *= corr;
                oL[mb][rr * 2 + 1] *= corr;
            }
        }

        // ---- O += P V ; l += P e0 (P via ldmatrix, V via x4.trans) ----
        #pragma unroll
        for (int ks = 0; ks < 4; ++ks) {
            uint32_t af[2][4];
            const uint32_t ckP = (uint32_t)(2 * ks + asel);
            #pragma unroll
            for (int mb = 0; mb < 2; ++mb) {
                int row = wid * 32 + mb * 16 + arow;
                uint32_t addr = sS + (uint32_t)(row * 128)
                              + ((ckP ^ (uint32_t)(row & 7)) << 4);
                ldsm_x4(af[mb], addr);
            }
            mma_f16(oL[0], af[0], ones0, ones1);
            mma_f16(oL[1], af[1], ones0, ones1);

            const int vrow = ks * 16 + (lane & 15);
            const uint32_t rowbase = sV[buf] + (uint32_t)vrow * 128u;
            const uint32_t rx = (uint32_t)(vrow & 7) << 4;
            const uint32_t nsel = (uint32_t)(lane >> 4);   // 0 or 1
            #pragma unroll
            for (int nb = 0; nb < 8; nb += 2) {
                uint32_t addr = rowbase + ((((uint32_t)nb + nsel) << 4) ^ rx);
                uint32_t t[4];
                ldsm_x4_t(t, addr);
                mma_f16(o[0][nb],     af[0], t[0], t[1]);
                mma_f16(o[1][nb],     af[1], t[0], t[1]);
                mma_f16(o[0][nb + 1], af[0], t[2], t[3]);
                mma_f16(o[1][nb + 1], af[1], t[2], t[3]);
            }
        }
        __syncthreads();
    }

    // ---- epilogue: recover l from oL col0, normalize, residual, stats ----
    float colS[16], colQ[16];
    #pragma unroll
    for (int i = 0; i < 16; ++i) { colS[i] = 0.f; colQ[i] = 0.f; }

    const int qsrc = lane & ~3;           // lane of tg==0 in this quad
    #pragma unroll
    for (int mb = 0; mb < 2; ++mb) {
        #pragma unroll
        for (int rr = 0; rr < 2; ++rr) {
            float lsum = __shfl_sync(0xffffffffu, oL[mb][rr * 2], qsrc);
            float inv = 1.0f / lsum;
            int grow = qt * 128 + wid * 32 + mb * 16 + rr * 8 + g;
            size_t rowoff = nbase + (size_t)grow * DM + hcol;
            #pragma unroll
            for (int nb = 0; nb < 8; ++nb) {
                int c = nb * 8 + tg * 2;
                float2 qv = *(const float2*)(query + rowoff + c);
                float2 w;
                w.x = o[mb][nb][rr * 2 + 0] * inv + qv.x;
                w.y = o[mb][nb][rr * 2 + 1] * inv + qv.y;
                *(float2*)(gRes + rowoff + c) = w;
                colS[2 * nb]     += w.x;
                colQ[2 * nb]     += w.x * w.x;
                colS[2 * nb + 1] += w.y;
                colQ[2 * nb + 1] += w.y * w.y;
            }
        }
    }
    #pragma unroll
    for (int i = 0; i < 16; ++i) {
        #pragma unroll
        for (int off = 4; off < 32; off <<= 1) {
            colS[i] += __shfl_xor_sync(0xffffffffu, colS[i], off);
            colQ[i] += __shfl_xor_sync(0xffffffffu, colQ[i], off);
        }
    }
    float* redS = (float*)ash;          // [4][64]
    float* redQ = redS + 256;           // [4][64]
    if (g == 0) {
        #pragma unroll
        for (int i = 0; i < 16; ++i) {
            int c = (i >> 1) * 8 + tg * 2 + (i & 1);
            redS[wid * 64 + c] = colS[i];
            redQ[wid * 64 + c] = colQ[i];
        }
    }
    __syncthreads();
    if (tid < 64) {
        float s = redS[tid] + redS[64 + tid] + redS[128 + tid] + redS[192 + tid];
        float q = redQ[tid] + redQ[64 + tid] + redQ[128 + tid] + redQ[192 + tid];
        int chunk = n * 16 + qt;
        gPartS[chunk * DM + hcol + tid] = s;
        gPartQ[chunk * DM + hcol + tid] = q;
    }
}

// ---------------------------------------------------------------------------
// BatchNorm: final stats + fused normalize
// ---------------------------------------------------------------------------
__global__ void __launch_bounds__(256) colstats_final(const float* __restrict__ gamma,
                                                      const float* __restrict__ beta)
{
    const int cidx = threadIdx.x & 31;
    const int seg  = threadIdx.x >> 5;
    const int col  = blockIdx.x * 32 + cidx;
    float s = 0.f, q = 0.f;
    #pragma unroll
    for (int c = 0; c < 8; ++c) {
        int chunk = seg * 8 + c;
        s += gPartS[chunk * DM + col];
        q += gPartQ[chunk * DM + col];
    }
    __shared__ float shS[8][33], shQ[8][33];
    shS[seg][cidx] = s;
    shQ[seg][cidx] = q;
    __syncthreads();
    if (seg == 0) {
        float ts = 0.f, tq = 0.f;
        #pragma unroll
        for (int i = 0; i < 8; ++i) { ts += shS[i][cidx]; tq += shQ[i][cidx]; }
        const float invn = 1.0f / (float)MROWS;
        float mean = ts * invn;
        float var  = tq * invn - mean * mean;
        float inv  = rsqrtf(var + EPSBN);
        float a    = gamma[col] * inv;
        gColA[col] = a;
        gColB[col] = beta[col] - mean * a;
    }
}

// 4 float4 per thread: fewer blocks, more ILP on a pure-BW kernel
__global__ void __launch_bounds__(256) normalize_kernel(float* __restrict__ out)
{
    const size_t base = (size_t)blockIdx.x * 1024 + threadIdx.x;
    #pragma unroll
    for (int j = 0; j < 4; ++j) {
        const size_t idx = base + j * 256;
        float4 v = ((const float4*)gRes)[idx];
        int col = (int)((idx * 4) & (DM - 1));
        float4 r;
        r.x = v.x * gColA[col + 0] + gColB[col + 0];
        r.y = v.y * gColA[col + 1] + gColB[col + 1];
        r.z = v.z * gColA[col + 2] + gColB[col + 2];
        r.w = v.w * gColA[col + 3] + gColB[col + 3];
        ((float4*)out)[idx] = r;
    }
}

// ---------------------------------------------------------------------------
extern "C" void kernel_launch(void* const* d_in, const int* in_sizes, int n_in,
                              void* d_out, int out_size)
{
    const float* query = (const float*)d_in[0];
    const float* key   = (const float*)d_in[1];
    const float* Wq    = (const float*)d_in[2];
    const float* Wk    = (const float*)d_in[3];
    const float* Wv    = (const float*)d_in[4];
    const float* gamma = (const float*)d_in[5];
    const float* beta  = (const float*)d_in[6];
    float* out = (float*)d_out;

    conv_all<<<4864, 256>>>(query, key, Wq, Wk, Wv);

    const int gemm_smem = 6 * GSTG * 2;      // 98304 B
    cudaFuncSetAttribute(gemm_mma, cudaFuncAttributeMaxDynamicSharedMemorySize,
                         gemm_smem);
    dim3 gg(DM / 128, MROWS / 128, 3);
    gemm_mma<<<gg, 256, gemm_smem>>>();

    const int attn_smem = 65536 + 512;       // K/V + P + Q + ones
    cudaFuncSetAttribute(attn_mma, cudaFuncAttributeMaxDynamicSharedMemorySize,
                         attn_smem);
    dim3 ga(LQL / 128, HH, NB);
    attn_mma<<<ga, 128, attn_smem>>>(query);

    colstats_final<<<DM / 32, 256>>>(gamma, beta);

    const int total_f4 = MROWS * DM / 4;     // 2,097,152
    normalize_kernel<<<total_f4 / 1024, 256>>>(out);
}